// round 11
// baseline (speedup 1.0000x reference)
#include <cuda_runtime.h>
#include <cuda_bf16.h>
#include <stdint.h>

#define BS 8
#define CH 256
#define HH 128
#define WW 128
#define HW (HH*WW)          /* 16384 */
#define NA 9
#define KTOP 100
#define NDET (BS*KTOP)      /* 800 */
#define FDIM (CH*NA)        /* 2304 */
#define KSPL (3*FDIM)       /* 6912 */
#define MPAD 832            /* 13*64 */
#define HID 1024
#define NBINS 4096
#define CAND 512
#define SAFE_BIN 4088
#define BHW (NA*HW)         /* 147456 */
#define HMTOT (BS*BHW)      /* 1179648 */
#define HBLK 18

/* front-kernel block layout (bid-ordered: producers before consumers) */
#define NB_HIST (HBLK*BS)              /* 144 */
#define SEL_BASE NB_HIST               /* 144 */
#define ROI_BASE (SEL_BASE + BS)       /* 152 */
#define PREP_BASE (ROI_BASE + NDET)    /* 952 */
#define NB_PREP ((FDIM/64)*(HID/32))   /* 1152 */
#define NB_FRONT (PREP_BASE + NB_PREP) /* 2104 */

#define OFF_HM    0
#define OFF_WH1   1179648
#define OFF_OFF1  1182848
#define OFF_CLS1  1184448
#define OFF_WH2   1185248
#define OFF_OFF2  1188448
#define OFF_S2CLS 1190048
#define OFF_S2WH  1198048
#define OFF_INDS  1201248
#define OFF_VAL   1202048

// ---------------- scratch ----------------
__device__ int                g_hist[BS*NBINS];
__device__ int                g_ccnt[BS];
__device__ unsigned long long g_cand[BS*CAND];
__device__ float              g_boxes[NDET*4];
__device__ int                g_histdone;         // reset in k_gemm_mma
__device__ int                g_boxready[BS];     // reset in k_gemm_mma
__device__ __align__(16) __nv_bfloat16 g_abf[MPAD*KSPL];   // rows >= NDET stay zero forever
__device__ __align__(16) __nv_bfloat16 g_bbf[HID*KSPL];

__device__ __forceinline__ uint32_t smem_u32(const void* p) {
    uint32_t a;
    asm("{ .reg .u64 t; cvta.to.shared.u64 t, %1; cvt.u32.u64 %0, t; }" : "=r"(a) : "l"(p));
    return a;
}
__device__ __forceinline__ void cp_async16(uint32_t d, const void* s) {
    unsigned long long g;
    asm("cvta.to.global.u64 %0, %1;" : "=l"(g) : "l"(s));
    asm volatile("cp.async.cg.shared.global [%0], [%1], 16;" :: "r"(d), "l"(g));
}
__device__ __forceinline__ void ldmatrix_x4(uint32_t* r, uint32_t addr) {
    asm volatile("ldmatrix.sync.aligned.m8n8.x4.shared.b16 {%0,%1,%2,%3}, [%4];"
        : "=r"(r[0]), "=r"(r[1]), "=r"(r[2]), "=r"(r[3]) : "r"(addr));
}
__device__ __forceinline__ void mma16816(float* d, const uint32_t* a, const uint32_t* b) {
    asm volatile("mma.sync.aligned.m16n8k16.row.col.f32.bf16.bf16.f32 "
        "{%0,%1,%2,%3}, {%4,%5,%6,%7}, {%8,%9}, {%0,%1,%2,%3};"
        : "+f"(d[0]), "+f"(d[1]), "+f"(d[2]), "+f"(d[3])
        : "r"(a[0]), "r"(a[1]), "r"(a[2]), "r"(a[3]), "r"(b[0]), "r"(b[1]));
}
__device__ __forceinline__ int val_bin(float v) {
    int bin = (int)(v * (float)NBINS);
    return bin < 0 ? 0 : (bin > NBINS-1 ? NBINS-1 : bin);
}
__device__ __forceinline__ unsigned long long make_key(float v, int il) {
    int a = il / HW, pix = il - a*HW;
    unsigned iflat = (unsigned)(pix * NA + a);
    return ((unsigned long long)__float_as_uint(v) << 32) | (0xFFFFFFFFu - iflat);
}

// ================ fused front kernel ================
__global__ void __launch_bounds__(256) k_front(const float* __restrict__ hm,
                       const float* __restrict__ feat,
                       const float* __restrict__ wh,  const float* __restrict__ offs,
                       const float* __restrict__ wfc1,
                       const float* __restrict__ bcls, const float* __restrict__ bwh,
                       float* __restrict__ out) {
    __shared__ union {
        int hist[NBINS];
        struct { unsigned long long sk[CAND]; int thr; int ovf; } sel;
        float prep[64][33];
    } u;
    int bid = blockIdx.x, tid = threadIdx.x;

    // ---------- role 1: hist + copy + candidate collect ----------
    if (bid < NB_HIST) {
        int b = bid / HBLK, xblk = bid % HBLK;
        #pragma unroll
        for (int q = 0; q < NBINS/256; ++q) u.hist[tid + q*256] = 0;
        __syncthreads();
        const int chunk = BHW/4/HBLK;
        int base4 = b*(BHW/4) + xblk*chunk;
        const float4* src = (const float4*)hm + base4;
        float4* dst = (float4*)(out + OFF_HM) + base4;
        int il_base = xblk*chunk*4;
        #pragma unroll
        for (int q = 0; q < chunk/256; ++q) {
            int i = tid + q*256;
            float4 v4 = src[i];
            dst[i] = v4;
            float vv[4] = {v4.x, v4.y, v4.z, v4.w};
            #pragma unroll
            for (int e = 0; e < 4; ++e) {
                int bin = val_bin(vv[e]);
                atomicAdd(&u.hist[bin], 1);
                if (bin >= SAFE_BIN) {
                    unsigned long long key = make_key(vv[e], il_base + i*4 + e);
                    int p = atomicAdd(&g_ccnt[b], 1);
                    if (p < CAND) g_cand[b*CAND + p] = key;
                }
            }
        }
        __syncthreads();
        #pragma unroll
        for (int q = 0; q < NBINS/256; ++q) {
            int i = tid + q*256;
            int c = u.hist[i];
            if (c) atomicAdd(&g_hist[b*NBINS + i], c);
        }
        __threadfence();
        __syncthreads();
        if (tid == 0) atomicAdd(&g_histdone, 1);
        return;
    }

    // ---------- role 2: select ----------
    if (bid < ROI_BASE) {
        int b = bid - SEL_BASE, lane = tid & 31, wid = tid >> 5;
        if (tid == 0) { while (atomicAdd(&g_histdone, 0) < NB_HIST) { } }
        __syncthreads();
        __threadfence();

        int rawcnt = g_ccnt[b];
        int C = rawcnt < CAND ? rawcnt : CAND;
        #pragma unroll
        for (int q = 0; q < CAND/256; ++q) {
            int i = tid + q*256;
            u.sel.sk[i] = (i < C) ? g_cand[b*CAND + i] : 0ULL;
        }
        if (wid == 0) {
            int cum = 0, found = 0, t = 0;
            for (int base = NBINS-32; base >= 0 && !found; base -= 32) {
                int c = g_hist[b*NBINS + base + lane];
                #pragma unroll
                for (int o = 1; o < 32; o <<= 1) {
                    int uu = __shfl_down_sync(0xffffffffu, c, o);
                    if (lane < 32 - o) c += uu;
                }
                unsigned m = __ballot_sync(0xffffffffu, cum + c >= KTOP);
                if (m) { t = base + (31 - __clz(m)); found = 1; }
                else cum += __shfl_sync(0xffffffffu, c, 0);
            }
            if (lane == 0) { u.sel.thr = t; u.sel.ovf = 0; }
        }
        __syncthreads();
        int thr = u.sel.thr;

        if (rawcnt > CAND || thr < SAFE_BIN) {        // exactness fallback
            const float* hb = hm + (size_t)b * BHW;
            for (int i = tid; i < BHW; i += 256) {
                float v = hb[i];
                if (val_bin(v) >= thr) {
                    int p = atomicAdd(&u.sel.ovf, 1);
                    if (p < CAND) u.sel.sk[p] = make_key(v, i);
                }
            }
            __syncthreads();
            int C2 = u.sel.ovf < CAND ? u.sel.ovf : CAND;
            #pragma unroll
            for (int q = 0; q < CAND/256; ++q) {
                int i = tid + q*256;
                if (i >= C2) u.sel.sk[i] = 0ULL;
            }
        }
        for (int i = tid; i < NBINS; i += 256) g_hist[b*NBINS + i] = 0;
        if (tid == 0) g_ccnt[b] = 0;

        for (int k = 2; k <= CAND; k <<= 1)
            for (int j = k >> 1; j > 0; j >>= 1) {
                __syncthreads();
                int idx = ((tid & ~(j - 1)) << 1) | (tid & (j - 1));
                int ixj = idx | j;
                unsigned long long x = u.sel.sk[idx], y = u.sel.sk[ixj];
                bool desc = ((idx & k) == 0);
                if (desc ? (x < y) : (x > y)) { u.sel.sk[idx] = y; u.sel.sk[ixj] = x; }
            }
        __syncthreads();

        if (tid < KTOP) {
            int j = b*KTOP + tid;
            unsigned long long m = u.sel.sk[tid];
            float v = __uint_as_float((unsigned)(m >> 32));
            int iflat = (int)(0xFFFFFFFFu - (unsigned)(m & 0xFFFFFFFFu));
            int cls1 = iflat % NA;
            int pos  = iflat / NA;
            int inds = pos + b * HW;
            int a2 = inds % NA;        // select_tensor batch-0 quirk
            int p2 = inds / NA;
            float w0 = wh[(a2*4+0)*HW + p2];
            float w1 = wh[(a2*4+1)*HW + p2];
            float w2 = wh[(a2*4+2)*HW + p2];
            float w3 = wh[(a2*4+3)*HW + p2];
            float o0 = offs[(a2*2+0)*HW + p2];
            float o1 = offs[(a2*2+1)*HW + p2];
            float xs = (float)(inds % WW) + o0;
            float ys = (float)(inds / WW) + o1;
            g_boxes[j*4+0] = xs + w0; g_boxes[j*4+1] = ys + w1;
            g_boxes[j*4+2] = xs + w2; g_boxes[j*4+3] = ys + w3;
            out[OFF_WH1 + j*4+0] = w0; out[OFF_WH1 + j*4+1] = w1;
            out[OFF_WH1 + j*4+2] = w2; out[OFF_WH1 + j*4+3] = w3;
            out[OFF_WH2 + j*4+0] = w0; out[OFF_WH2 + j*4+1] = w1;
            out[OFF_WH2 + j*4+2] = w2; out[OFF_WH2 + j*4+3] = w3;
            out[OFF_OFF1 + j*2+0] = o0; out[OFF_OFF1 + j*2+1] = o1;
            out[OFF_OFF2 + j*2+0] = o0; out[OFF_OFF2 + j*2+1] = o1;
            out[OFF_CLS1 + j] = (float)cls1;
            out[OFF_INDS + j] = (float)inds;
            out[OFF_VAL  + j] = v;
            #pragma unroll
            for (int q = 0; q < 10; ++q) out[OFF_S2CLS + j*10 + q] = bcls[q];
            #pragma unroll
            for (int q = 0; q < 4;  ++q) out[OFF_S2WH  + j*4  + q] = bwh[q];
        }
        __threadfence();
        __syncthreads();
        if (tid == 0) atomicExch(&g_boxready[b], 1);
        return;
    }

    // ---------- role 3: ROI align -> bf16 split A' ----------
    if (bid < PREP_BASE) {
        int j = bid - ROI_BASE;
        int c = tid;
        int b = j / KTOP;
        if (tid == 0) { while (atomicAdd(&g_boxready[b], 0) == 0) { } }
        __syncthreads();
        __threadfence();
        float x1b = g_boxes[j*4+0], y1b = g_boxes[j*4+1];
        float x2b = g_boxes[j*4+2], y2b = g_boxes[j*4+3];
        float rw = fmaxf(x2b - x1b, 1.0f);
        float rh = fmaxf(y2b - y1b, 1.0f);
        float bw = rw / 3.0f;
        float bh = rh / 3.0f;
        const float* fb = feat + ((size_t)b*CH + c) * HW;
        #pragma unroll
        for (int pt = 0; pt < 9; ++pt) {
            int gy = pt / 3, gx = pt % 3;
            float sy = __fadd_rn(y1b, __fmul_rn((float)gy + 0.5f, bh));
            float sx = __fadd_rn(x1b, __fmul_rn((float)gx + 0.5f, bw));
            bool inv = (sy < -1.0f) || (sy > (float)HH) || (sx < -1.0f) || (sx > (float)WW);
            float r = 0.0f;
            if (!inv) {
                float y = fminf(fmaxf(sy, 0.0f), (float)(HH-1));
                float x = fminf(fmaxf(sx, 0.0f), (float)(WW-1));
                int y0 = (int)floorf(y), x0 = (int)floorf(x);
                int y1i = min(y0 + 1, HH-1), x1i = min(x0 + 1, WW-1);
                float ly = __fadd_rn(y, -(float)y0);
                float lx = __fadd_rn(x, -(float)x0);
                float hy = __fadd_rn(1.0f, -ly);
                float hx = __fadd_rn(1.0f, -lx);
                float v00, v01, v10, v11;
                if ((x0 & 1) == 0 && x0 < HH-1) {
                    float2 t0 = *(const float2*)(fb + y0 *WW + x0);
                    float2 t1 = *(const float2*)(fb + y1i*WW + x0);
                    v00 = t0.x; v01 = t0.y; v10 = t1.x; v11 = t1.y;
                } else {
                    v00 = fb[y0 *WW + x0 ]; v01 = fb[y0 *WW + x1i];
                    v10 = fb[y1i*WW + x0 ]; v11 = fb[y1i*WW + x1i];
                }
                r = __fadd_rn(__fadd_rn(__fadd_rn(
                        __fmul_rn(__fmul_rn(hy,hx), v00),
                        __fmul_rn(__fmul_rn(hy,lx), v01)),
                        __fmul_rn(__fmul_rn(ly,hx), v10)),
                        __fmul_rn(__fmul_rn(ly,lx), v11));
            }
            __nv_bfloat16 hi = __float2bfloat16(r);
            __nv_bfloat16 lo = __float2bfloat16(__fadd_rn(r, -__bfloat162float(hi)));
            size_t base = (size_t)j*KSPL + 3*(pt*CH + c);
            g_abf[base+0] = hi;
            g_abf[base+1] = hi;
            g_abf[base+2] = lo;
        }
        return;
    }

    // ---------- role 4: B' prep ----------
    {
        int pid = bid - PREP_BASE;
        int t0 = (pid % (FDIM/64)) * 64, n0 = (pid / (FDIM/64)) * 32;
        int wp = tid >> 5, ln = tid & 31;
        #pragma unroll
        for (int q = 0; q < 8; ++q) {
            int tl = wp*8 + q;
            int t = t0 + tl;
            int pt = t >> 8, c = t & 255;
            u.prep[tl][ln] = wfc1[(size_t)(c*NA + pt)*HID + n0 + ln];
        }
        __syncthreads();
        int n = tid >> 3, tg = tid & 7;
        __nv_bfloat16 obuf[24];
        #pragma unroll
        for (int q = 0; q < 8; ++q) {
            float v = u.prep[tg*8 + q][n];
            __nv_bfloat16 hi = __float2bfloat16(v);
            __nv_bfloat16 lo = __float2bfloat16(v - __bfloat162float(hi));
            obuf[q*3+0] = hi; obuf[q*3+1] = lo; obuf[q*3+2] = hi;
        }
        uint4* dst = (uint4*)((char*)g_bbf + (size_t)(n0 + n)*(KSPL*2) + 6*(size_t)(t0 + tg*8));
        const uint4* sv = (const uint4*)obuf;
        dst[0] = sv[0]; dst[1] = sv[1]; dst[2] = sv[2];
    }
}

// ---------------- fc1 GEMM (64x64 tiles, 3-stage) + fused stage2 heads ----------------
#define BM 64
#define BN 64
#define STAGE_BYTES 16384     /* A 8KB + B 8KB */
#define KT_TOTAL (KSPL/64)    /* 108 */
__global__ void __launch_bounds__(256) k_gemm_mma(const float* __restrict__ bias,
                                                  const float* __restrict__ wcls,
                                                  const float* __restrict__ wwh,
                                                  float* __restrict__ out) {
    __shared__ __align__(1024) char smem[3*STAGE_BYTES];  // 48KB
    int tid = threadIdx.x, lane = tid & 31, w = tid >> 5;
    int bm = blockIdx.x * BM, bn = blockIdx.y * BN;
    int wm = w >> 1, wn = w & 1;           // wm 0..3 (16 rows), wn 0..1 (32 cols)

    if (blockIdx.x == 0 && blockIdx.y == 0 && tid == 0) {
        g_histdone = 0;
        #pragma unroll
        for (int b = 0; b < BS; ++b) g_boxready[b] = 0;
    }

    const char* aG = (const char*)g_abf + (size_t)bm * (KSPL*2);
    const char* bG = (const char*)g_bbf + (size_t)bn * (KSPL*2);

    float acc[4][4];
    #pragma unroll
    for (int ni = 0; ni < 4; ++ni)
        #pragma unroll
        for (int e = 0; e < 4; ++e) acc[ni][e] = 0.0f;

    #define ISSUE_STAGE(kt, st) do {                                           \
        char* As_ = smem + (st)*STAGE_BYTES;                                   \
        char* Bs_ = As_ + 8192;                                                \
        _Pragma("unroll")                                                      \
        for (int q = 0; q < 2; ++q) {                                          \
            int id = tid + q*256;                                              \
            int r = id >> 3, c = id & 7;                                       \
            uint32_t d = smem_u32(As_ + r*128 + ((c ^ (r & 7)) * 16));         \
            cp_async16(d, aG + (size_t)r*(KSPL*2) + (kt)*128 + c*16);          \
        }                                                                      \
        _Pragma("unroll")                                                      \
        for (int q = 0; q < 2; ++q) {                                          \
            int id = tid + q*256;                                              \
            int r = id >> 3, c = id & 7;                                       \
            uint32_t d = smem_u32(Bs_ + r*128 + ((c ^ (r & 7)) * 16));         \
            cp_async16(d, bG + (size_t)r*(KSPL*2) + (kt)*128 + c*16);          \
        }                                                                      \
        asm volatile("cp.async.commit_group;" ::: "memory");                   \
    } while (0)

    ISSUE_STAGE(0, 0);
    ISSUE_STAGE(1, 1);

    for (int kt = 0; kt < KT_TOTAL; ++kt) {
        int st = kt - (kt/3)*3;               // kt % 3
        if (kt + 2 < KT_TOTAL) {
            int st2 = (kt+2) - ((kt+2)/3)*3;
            ISSUE_STAGE(kt + 2, st2);
            asm volatile("cp.async.wait_group 2;" ::: "memory");
        } else if (kt + 1 < KT_TOTAL) {
            asm volatile("cp.async.wait_group 1;" ::: "memory");
        } else {
            asm volatile("cp.async.wait_group 0;" ::: "memory");
        }
        __syncthreads();

        char* As = smem + st*STAGE_BYTES;
        char* Bs = As + 8192;

        uint32_t af[2][4], bf2[2][2][4];
        {   // preload kk = 0
            int r = wm*16 + (lane & 15);
            int c = (lane >> 4);
            ldmatrix_x4(af[0], smem_u32(As + r*128 + ((c ^ (r & 7)) * 16)));
            int grp = lane >> 3;
            #pragma unroll
            for (int nj = 0; nj < 2; ++nj) {
                int rb = wn*32 + nj*16 + (grp >> 1)*8 + (lane & 7);
                int cb = (grp & 1);
                ldmatrix_x4(bf2[0][nj], smem_u32(Bs + rb*128 + ((cb ^ (rb & 7)) * 16)));
            }
        }
        #pragma unroll
        for (int kk = 0; kk < 4; ++kk) {
            int cur = kk & 1, nxt = cur ^ 1;
            if (kk < 3) {
                int r = wm*16 + (lane & 15);
                int c = (kk+1)*2 + (lane >> 4);
                ldmatrix_x4(af[nxt], smem_u32(As + r*128 + ((c ^ (r & 7)) * 16)));
                int grp = lane >> 3;
                #pragma unroll
                for (int nj = 0; nj < 2; ++nj) {
                    int rb = wn*32 + nj*16 + (grp >> 1)*8 + (lane & 7);
                    int cb = (kk+1)*2 + (grp & 1);
                    ldmatrix_x4(bf2[nxt][nj], smem_u32(Bs + rb*128 + ((cb ^ (rb & 7)) * 16)));
                }
            }
            #pragma unroll
            for (int ni = 0; ni < 4; ++ni)
                mma16816(acc[ni], af[cur], &bf2[cur][ni >> 1][(ni & 1) * 2]);
        }
        __syncthreads();
    }

    // ---- fused stage2 epilogue ----
    float* sWq = (float*)smem;
    float* sBias = sWq + 14*64;
    for (int i = tid; i < 14*64; i += 256) {
        int q = i >> 6, c = i & 63;
        sWq[i] = (q < 10) ? wcls[(size_t)(bn + c)*10 + q]
                          : wwh[(size_t)(bn + c)*4 + (q - 10)];
    }
    if (tid < 64) sBias[tid] = bias[bn + tid];
    __syncthreads();

    float psA[14], psB[14];
    #pragma unroll
    for (int q = 0; q < 14; ++q) { psA[q] = 0.0f; psB[q] = 0.0f; }
    #pragma unroll
    for (int ni = 0; ni < 4; ++ni) {
        int cl = wn*32 + ni*8 + (lane & 3)*2;
        float b0 = sBias[cl], b1 = sBias[cl+1];
        float hA0 = fmaxf(acc[ni][0] + b0, 0.0f);
        float hA1 = fmaxf(acc[ni][1] + b1, 0.0f);
        float hB0 = fmaxf(acc[ni][2] + b0, 0.0f);
        float hB1 = fmaxf(acc[ni][3] + b1, 0.0f);
        #pragma unroll
        for (int q = 0; q < 14; ++q) {
            float2 ww = *(const float2*)&sWq[q*64 + cl];
            psA[q] += hA0*ww.x + hA1*ww.y;
            psB[q] += hB0*ww.x + hB1*ww.y;
        }
    }
    #pragma unroll
    for (int o = 1; o < 4; o <<= 1) {
        #pragma unroll
        for (int q = 0; q < 14; ++q) {
            psA[q] += __shfl_xor_sync(0xffffffffu, psA[q], o);
            psB[q] += __shfl_xor_sync(0xffffffffu, psB[q], o);
        }
    }
    if ((lane & 3) == 0) {
        int rA = bm + wm*16 + (lane >> 2);
        int rB = rA + 8;
        if (rA < NDET) {
            #pragma unroll
            for (int q = 0; q < 14; ++q) {
                float* dst = (q < 10) ? &out[OFF_S2CLS + (size_t)rA*10 + q]
                                      : &out[OFF_S2WH  + (size_t)rA*4  + (q-10)];
                atomicAdd(dst, psA[q]);
            }
        }
        if (rB < NDET) {
            #pragma unroll
            for (int q = 0; q < 14; ++q) {
                float* dst = (q < 10) ? &out[OFF_S2CLS + (size_t)rB*10 + q]
                                      : &out[OFF_S2WH  + (size_t)rB*4  + (q-10)];
                atomicAdd(dst, psB[q]);
            }
        }
    }
}

// ---------------- launch ----------------
extern "C" void kernel_launch(void* const* d_in, const int* in_sizes, int n_in,
                              void* d_out, int out_size) {
    const float* feat  = (const float*)d_in[0];
    const float* hm    = (const float*)d_in[1];
    const float* wh    = (const float*)d_in[2];
    const float* offs  = (const float*)d_in[3];
    const float* wfc1  = (const float*)d_in[4];
    const float* bfc1  = (const float*)d_in[5];
    const float* wcls  = (const float*)d_in[6];
    const float* bcls  = (const float*)d_in[7];
    const float* wwh   = (const float*)d_in[8];
    const float* bwh   = (const float*)d_in[9];
    float* out = (float*)d_out;

    k_front<<<NB_FRONT, 256>>>(hm, feat, wh, offs, wfc1, bcls, bwh, out);
    k_gemm_mma<<<dim3(MPAD/BM, HID/BN), 256>>>(bfc1, wcls, wwh, out);
}

// round 12
// speedup vs baseline: 1.5600x; 1.5600x over previous
#include <cuda_runtime.h>
#include <cuda_bf16.h>
#include <stdint.h>

#define BS 8
#define CH 256
#define HH 128
#define WW 128
#define HW (HH*WW)          /* 16384 */
#define NA 9
#define KTOP 100
#define NDET (BS*KTOP)      /* 800 */
#define FDIM (CH*NA)        /* 2304 */
#define KSPL (3*FDIM)       /* 6912 */
#define MPAD 896            /* 7*128 */
#define HID 1024
#define NBINS 4096
#define CAND 512
#define SAFE_BIN 4088
#define BHW (NA*HW)         /* 147456 */
#define HMTOT (BS*BHW)      /* 1179648 */
#define HBLK 18

/* front-kernel block layout (bid-ordered: producers before consumers) */
#define NB_HIST (HBLK*BS)              /* 144 */
#define SEL_BASE NB_HIST               /* 144 */
#define ROI_BASE (SEL_BASE + BS)       /* 152 */
#define PREP_BASE (ROI_BASE + NDET)    /* 952 */
#define NB_PREP ((FDIM/64)*(HID/32))   /* 1152 */
#define NB_FRONT (PREP_BASE + NB_PREP) /* 2104 */

#define OFF_HM    0
#define OFF_WH1   1179648
#define OFF_OFF1  1182848
#define OFF_CLS1  1184448
#define OFF_WH2   1185248
#define OFF_OFF2  1188448
#define OFF_S2CLS 1190048
#define OFF_S2WH  1198048
#define OFF_INDS  1201248
#define OFF_VAL   1202048

// ---------------- scratch ----------------
__device__ int                g_hist[BS*NBINS];
__device__ int                g_ccnt[BS];
__device__ unsigned long long g_cand[BS*CAND];
__device__ float              g_boxes[NDET*4];
__device__ int                g_histdone;         // reset in k_gemm_mma
__device__ int                g_boxready[BS];     // reset in k_gemm_mma
__device__ __align__(16) __nv_bfloat16 g_abf[MPAD*KSPL];   // rows >= NDET stay zero forever
__device__ __align__(16) __nv_bfloat16 g_bbf[HID*KSPL];

__device__ __forceinline__ uint32_t smem_u32(const void* p) {
    uint32_t a;
    asm("{ .reg .u64 t; cvta.to.shared.u64 t, %1; cvt.u32.u64 %0, t; }" : "=r"(a) : "l"(p));
    return a;
}
__device__ __forceinline__ void cp_async16(uint32_t d, const void* s) {
    unsigned long long g;
    asm("cvta.to.global.u64 %0, %1;" : "=l"(g) : "l"(s));
    asm volatile("cp.async.cg.shared.global [%0], [%1], 16;" :: "r"(d), "l"(g));
}
__device__ __forceinline__ void ldmatrix_x4(uint32_t* r, uint32_t addr) {
    asm volatile("ldmatrix.sync.aligned.m8n8.x4.shared.b16 {%0,%1,%2,%3}, [%4];"
        : "=r"(r[0]), "=r"(r[1]), "=r"(r[2]), "=r"(r[3]) : "r"(addr));
}
__device__ __forceinline__ void mma16816(float* d, const uint32_t* a, const uint32_t* b) {
    asm volatile("mma.sync.aligned.m16n8k16.row.col.f32.bf16.bf16.f32 "
        "{%0,%1,%2,%3}, {%4,%5,%6,%7}, {%8,%9}, {%0,%1,%2,%3};"
        : "+f"(d[0]), "+f"(d[1]), "+f"(d[2]), "+f"(d[3])
        : "r"(a[0]), "r"(a[1]), "r"(a[2]), "r"(a[3]), "r"(b[0]), "r"(b[1]));
}
__device__ __forceinline__ int val_bin(float v) {
    int bin = (int)(v * (float)NBINS);
    return bin < 0 ? 0 : (bin > NBINS-1 ? NBINS-1 : bin);
}
__device__ __forceinline__ unsigned long long make_key(float v, int il) {
    int a = il / HW, pix = il - a*HW;
    unsigned iflat = (unsigned)(pix * NA + a);
    return ((unsigned long long)__float_as_uint(v) << 32) | (0xFFFFFFFFu - iflat);
}

// ================ fused front kernel (unchanged from R10) ================
__global__ void __launch_bounds__(256) k_front(const float* __restrict__ hm,
                       const float* __restrict__ feat,
                       const float* __restrict__ wh,  const float* __restrict__ offs,
                       const float* __restrict__ wfc1,
                       const float* __restrict__ bcls, const float* __restrict__ bwh,
                       float* __restrict__ out) {
    __shared__ union {
        int hist[NBINS];
        struct { unsigned long long sk[CAND]; int thr; int ovf; } sel;
        float prep[64][33];
    } u;
    int bid = blockIdx.x, tid = threadIdx.x;

    // ---------- role 1: hist + copy + candidate collect ----------
    if (bid < NB_HIST) {
        int b = bid / HBLK, xblk = bid % HBLK;
        #pragma unroll
        for (int q = 0; q < NBINS/256; ++q) u.hist[tid + q*256] = 0;
        __syncthreads();
        const int chunk = BHW/4/HBLK;
        int base4 = b*(BHW/4) + xblk*chunk;
        const float4* src = (const float4*)hm + base4;
        float4* dst = (float4*)(out + OFF_HM) + base4;
        int il_base = xblk*chunk*4;
        #pragma unroll
        for (int q = 0; q < chunk/256; ++q) {
            int i = tid + q*256;
            float4 v4 = src[i];
            dst[i] = v4;
            float vv[4] = {v4.x, v4.y, v4.z, v4.w};
            #pragma unroll
            for (int e = 0; e < 4; ++e) {
                int bin = val_bin(vv[e]);
                atomicAdd(&u.hist[bin], 1);
                if (bin >= SAFE_BIN) {
                    unsigned long long key = make_key(vv[e], il_base + i*4 + e);
                    int p = atomicAdd(&g_ccnt[b], 1);
                    if (p < CAND) g_cand[b*CAND + p] = key;
                }
            }
        }
        __syncthreads();
        #pragma unroll
        for (int q = 0; q < NBINS/256; ++q) {
            int i = tid + q*256;
            int c = u.hist[i];
            if (c) atomicAdd(&g_hist[b*NBINS + i], c);
        }
        __threadfence();
        __syncthreads();
        if (tid == 0) atomicAdd(&g_histdone, 1);
        return;
    }

    // ---------- role 2: select ----------
    if (bid < ROI_BASE) {
        int b = bid - SEL_BASE, lane = tid & 31, wid = tid >> 5;
        if (tid == 0) { while (atomicAdd(&g_histdone, 0) < NB_HIST) { } }
        __syncthreads();
        __threadfence();

        int rawcnt = g_ccnt[b];
        int C = rawcnt < CAND ? rawcnt : CAND;
        #pragma unroll
        for (int q = 0; q < CAND/256; ++q) {
            int i = tid + q*256;
            u.sel.sk[i] = (i < C) ? g_cand[b*CAND + i] : 0ULL;
        }
        if (wid == 0) {
            int cum = 0, found = 0, t = 0;
            for (int base = NBINS-32; base >= 0 && !found; base -= 32) {
                int c = g_hist[b*NBINS + base + lane];
                #pragma unroll
                for (int o = 1; o < 32; o <<= 1) {
                    int uu = __shfl_down_sync(0xffffffffu, c, o);
                    if (lane < 32 - o) c += uu;
                }
                unsigned m = __ballot_sync(0xffffffffu, cum + c >= KTOP);
                if (m) { t = base + (31 - __clz(m)); found = 1; }
                else cum += __shfl_sync(0xffffffffu, c, 0);
            }
            if (lane == 0) { u.sel.thr = t; u.sel.ovf = 0; }
        }
        __syncthreads();
        int thr = u.sel.thr;

        if (rawcnt > CAND || thr < SAFE_BIN) {        // exactness fallback
            const float* hb = hm + (size_t)b * BHW;
            for (int i = tid; i < BHW; i += 256) {
                float v = hb[i];
                if (val_bin(v) >= thr) {
                    int p = atomicAdd(&u.sel.ovf, 1);
                    if (p < CAND) u.sel.sk[p] = make_key(v, i);
                }
            }
            __syncthreads();
            int C2 = u.sel.ovf < CAND ? u.sel.ovf : CAND;
            #pragma unroll
            for (int q = 0; q < CAND/256; ++q) {
                int i = tid + q*256;
                if (i >= C2) u.sel.sk[i] = 0ULL;
            }
        }
        for (int i = tid; i < NBINS; i += 256) g_hist[b*NBINS + i] = 0;
        if (tid == 0) g_ccnt[b] = 0;

        for (int k = 2; k <= CAND; k <<= 1)
            for (int j = k >> 1; j > 0; j >>= 1) {
                __syncthreads();
                int idx = ((tid & ~(j - 1)) << 1) | (tid & (j - 1));
                int ixj = idx | j;
                unsigned long long x = u.sel.sk[idx], y = u.sel.sk[ixj];
                bool desc = ((idx & k) == 0);
                if (desc ? (x < y) : (x > y)) { u.sel.sk[idx] = y; u.sel.sk[ixj] = x; }
            }
        __syncthreads();

        if (tid < KTOP) {
            int j = b*KTOP + tid;
            unsigned long long m = u.sel.sk[tid];
            float v = __uint_as_float((unsigned)(m >> 32));
            int iflat = (int)(0xFFFFFFFFu - (unsigned)(m & 0xFFFFFFFFu));
            int cls1 = iflat % NA;
            int pos  = iflat / NA;
            int inds = pos + b * HW;
            int a2 = inds % NA;        // select_tensor batch-0 quirk
            int p2 = inds / NA;
            float w0 = wh[(a2*4+0)*HW + p2];
            float w1 = wh[(a2*4+1)*HW + p2];
            float w2 = wh[(a2*4+2)*HW + p2];
            float w3 = wh[(a2*4+3)*HW + p2];
            float o0 = offs[(a2*2+0)*HW + p2];
            float o1 = offs[(a2*2+1)*HW + p2];
            float xs = (float)(inds % WW) + o0;
            float ys = (float)(inds / WW) + o1;
            g_boxes[j*4+0] = xs + w0; g_boxes[j*4+1] = ys + w1;
            g_boxes[j*4+2] = xs + w2; g_boxes[j*4+3] = ys + w3;
            out[OFF_WH1 + j*4+0] = w0; out[OFF_WH1 + j*4+1] = w1;
            out[OFF_WH1 + j*4+2] = w2; out[OFF_WH1 + j*4+3] = w3;
            out[OFF_WH2 + j*4+0] = w0; out[OFF_WH2 + j*4+1] = w1;
            out[OFF_WH2 + j*4+2] = w2; out[OFF_WH2 + j*4+3] = w3;
            out[OFF_OFF1 + j*2+0] = o0; out[OFF_OFF1 + j*2+1] = o1;
            out[OFF_OFF2 + j*2+0] = o0; out[OFF_OFF2 + j*2+1] = o1;
            out[OFF_CLS1 + j] = (float)cls1;
            out[OFF_INDS + j] = (float)inds;
            out[OFF_VAL  + j] = v;
            #pragma unroll
            for (int q = 0; q < 10; ++q) out[OFF_S2CLS + j*10 + q] = bcls[q];
            #pragma unroll
            for (int q = 0; q < 4;  ++q) out[OFF_S2WH  + j*4  + q] = bwh[q];
        }
        __threadfence();
        __syncthreads();
        if (tid == 0) atomicExch(&g_boxready[b], 1);
        return;
    }

    // ---------- role 3: ROI align -> bf16 split A' ----------
    if (bid < PREP_BASE) {
        int j = bid - ROI_BASE;
        int c = tid;
        int b = j / KTOP;
        if (tid == 0) { while (atomicAdd(&g_boxready[b], 0) == 0) { } }
        __syncthreads();
        __threadfence();
        float x1b = g_boxes[j*4+0], y1b = g_boxes[j*4+1];
        float x2b = g_boxes[j*4+2], y2b = g_boxes[j*4+3];
        float rw = fmaxf(x2b - x1b, 1.0f);
        float rh = fmaxf(y2b - y1b, 1.0f);
        float bw = rw / 3.0f;
        float bh = rh / 3.0f;
        const float* fb = feat + ((size_t)b*CH + c) * HW;
        #pragma unroll
        for (int pt = 0; pt < 9; ++pt) {
            int gy = pt / 3, gx = pt % 3;
            float sy = __fadd_rn(y1b, __fmul_rn((float)gy + 0.5f, bh));
            float sx = __fadd_rn(x1b, __fmul_rn((float)gx + 0.5f, bw));
            bool inv = (sy < -1.0f) || (sy > (float)HH) || (sx < -1.0f) || (sx > (float)WW);
            float r = 0.0f;
            if (!inv) {
                float y = fminf(fmaxf(sy, 0.0f), (float)(HH-1));
                float x = fminf(fmaxf(sx, 0.0f), (float)(WW-1));
                int y0 = (int)floorf(y), x0 = (int)floorf(x);
                int y1i = min(y0 + 1, HH-1), x1i = min(x0 + 1, WW-1);
                float ly = __fadd_rn(y, -(float)y0);
                float lx = __fadd_rn(x, -(float)x0);
                float hy = __fadd_rn(1.0f, -ly);
                float hx = __fadd_rn(1.0f, -lx);
                float v00, v01, v10, v11;
                if ((x0 & 1) == 0 && x0 < HH-1) {
                    float2 t0 = *(const float2*)(fb + y0 *WW + x0);
                    float2 t1 = *(const float2*)(fb + y1i*WW + x0);
                    v00 = t0.x; v01 = t0.y; v10 = t1.x; v11 = t1.y;
                } else {
                    v00 = fb[y0 *WW + x0 ]; v01 = fb[y0 *WW + x1i];
                    v10 = fb[y1i*WW + x0 ]; v11 = fb[y1i*WW + x1i];
                }
                r = __fadd_rn(__fadd_rn(__fadd_rn(
                        __fmul_rn(__fmul_rn(hy,hx), v00),
                        __fmul_rn(__fmul_rn(hy,lx), v01)),
                        __fmul_rn(__fmul_rn(ly,hx), v10)),
                        __fmul_rn(__fmul_rn(ly,lx), v11));
            }
            __nv_bfloat16 hi = __float2bfloat16(r);
            __nv_bfloat16 lo = __float2bfloat16(__fadd_rn(r, -__bfloat162float(hi)));
            size_t base = (size_t)j*KSPL + 3*(pt*CH + c);
            g_abf[base+0] = hi;
            g_abf[base+1] = hi;
            g_abf[base+2] = lo;
        }
        return;
    }

    // ---------- role 4: B' prep ----------
    {
        int pid = bid - PREP_BASE;
        int t0 = (pid % (FDIM/64)) * 64, n0 = (pid / (FDIM/64)) * 32;
        int wp = tid >> 5, ln = tid & 31;
        #pragma unroll
        for (int q = 0; q < 8; ++q) {
            int tl = wp*8 + q;
            int t = t0 + tl;
            int pt = t >> 8, c = t & 255;
            u.prep[tl][ln] = wfc1[(size_t)(c*NA + pt)*HID + n0 + ln];
        }
        __syncthreads();
        int n = tid >> 3, tg = tid & 7;
        __nv_bfloat16 obuf[24];
        #pragma unroll
        for (int q = 0; q < 8; ++q) {
            float v = u.prep[tg*8 + q][n];
            __nv_bfloat16 hi = __float2bfloat16(v);
            __nv_bfloat16 lo = __float2bfloat16(v - __bfloat162float(hi));
            obuf[q*3+0] = hi; obuf[q*3+1] = lo; obuf[q*3+2] = hi;
        }
        uint4* dst = (uint4*)((char*)g_bbf + (size_t)(n0 + n)*(KSPL*2) + 6*(size_t)(t0 + tg*8));
        const uint4* sv = (const uint4*)obuf;
        dst[0] = sv[0]; dst[1] = sv[1]; dst[2] = sv[2];
    }
}

// ---------------- fc1 GEMM (128x64, 2-stage, reg double-buffer) + fused stage2 ----------------
#define BM 128
#define BN 64
#define STAGE_BYTES 24576     /* A 16KB + B 8KB */
#define KT_TOTAL (KSPL/64)    /* 108 */
__global__ void __launch_bounds__(256) k_gemm_mma(const float* __restrict__ bias,
                                                  const float* __restrict__ wcls,
                                                  const float* __restrict__ wwh,
                                                  float* __restrict__ out) {
    __shared__ __align__(1024) char smem[2*STAGE_BYTES];
    int tid = threadIdx.x, lane = tid & 31, w = tid >> 5;
    int bm = blockIdx.x * BM, bn = blockIdx.y * BN;
    int wm = w >> 1, wn = w & 1;

    if (blockIdx.x == 0 && blockIdx.y == 0 && tid == 0) {
        g_histdone = 0;
        #pragma unroll
        for (int b = 0; b < BS; ++b) g_boxready[b] = 0;
    }

    const char* aG = (const char*)g_abf + (size_t)bm * (KSPL*2);
    const char* bG = (const char*)g_bbf + (size_t)bn * (KSPL*2);

    float acc[2][4][4];
    #pragma unroll
    for (int mi = 0; mi < 2; ++mi)
        #pragma unroll
        for (int ni = 0; ni < 4; ++ni)
            #pragma unroll
            for (int e = 0; e < 4; ++e) acc[mi][ni][e] = 0.0f;

    #define ISSUE_STAGE(kt, st) do {                                           \
        char* As_ = smem + (st)*STAGE_BYTES;                                   \
        char* Bs_ = As_ + 16384;                                               \
        _Pragma("unroll")                                                      \
        for (int q = 0; q < 4; ++q) {                                          \
            int id = tid + q*256;                                              \
            int r = id >> 3, c = id & 7;                                       \
            uint32_t d = smem_u32(As_ + r*128 + ((c ^ (r & 7)) * 16));         \
            cp_async16(d, aG + (size_t)r*(KSPL*2) + (kt)*128 + c*16);          \
        }                                                                      \
        _Pragma("unroll")                                                      \
        for (int q = 0; q < 2; ++q) {                                          \
            int id = tid + q*256;                                              \
            int r = id >> 3, c = id & 7;                                       \
            uint32_t d = smem_u32(Bs_ + r*128 + ((c ^ (r & 7)) * 16));         \
            cp_async16(d, bG + (size_t)r*(KSPL*2) + (kt)*128 + c*16);          \
        }                                                                      \
        asm volatile("cp.async.commit_group;" ::: "memory");                   \
    } while (0)

    // per-thread fragment smem addresses (kk-dependent column only)
    int ra = (lane & 15);               // a-frag row within 16-block
    int ca_hi = (lane >> 4);            // 0/1
    int grp = lane >> 3;
    int rb_in = (grp >> 1)*8 + (lane & 7);
    int cb_lo = (grp & 1);

    ISSUE_STAGE(0, 0);

    for (int kt = 0; kt < KT_TOTAL; ++kt) {
        int st = kt & 1;
        if (kt + 1 < KT_TOTAL) {
            ISSUE_STAGE(kt + 1, st ^ 1);
            asm volatile("cp.async.wait_group 1;" ::: "memory");
        } else {
            asm volatile("cp.async.wait_group 0;" ::: "memory");
        }
        __syncthreads();

        char* As = smem + st*STAGE_BYTES;
        char* Bs = As + 16384;

        uint32_t af[2][2][4], bf[2][2][4];
        // preload kk = 0
        {
            int c = ca_hi;
            #pragma unroll
            for (int mi = 0; mi < 2; ++mi) {
                int r = wm*32 + mi*16 + ra;
                ldmatrix_x4(af[0][mi], smem_u32(As + r*128 + ((c ^ (r & 7)) * 16)));
            }
            int cb = cb_lo;
            #pragma unroll
            for (int nj = 0; nj < 2; ++nj) {
                int r = wn*32 + nj*16 + rb_in;
                ldmatrix_x4(bf[0][nj], smem_u32(Bs + r*128 + ((cb ^ (r & 7)) * 16)));
            }
        }
        #pragma unroll
        for (int kk = 0; kk < 4; ++kk) {
            int cur = kk & 1, nxt = cur ^ 1;
            if (kk < 3) {
                int c = (kk+1)*2 + ca_hi;
                #pragma unroll
                for (int mi = 0; mi < 2; ++mi) {
                    int r = wm*32 + mi*16 + ra;
                    ldmatrix_x4(af[nxt][mi], smem_u32(As + r*128 + ((c ^ (r & 7)) * 16)));
                }
                int cb = (kk+1)*2 + cb_lo;
                #pragma unroll
                for (int nj = 0; nj < 2; ++nj) {
                    int r = wn*32 + nj*16 + rb_in;
                    ldmatrix_x4(bf[nxt][nj], smem_u32(Bs + r*128 + ((cb ^ (r & 7)) * 16)));
                }
            }
            #pragma unroll
            for (int mi = 0; mi < 2; ++mi)
                #pragma unroll
                for (int ni = 0; ni < 4; ++ni)
                    mma16816(acc[mi][ni], af[cur][mi], &bf[cur][ni >> 1][(ni & 1) * 2]);
        }
        __syncthreads();
    }

    // ---- fused stage2 epilogue ----
    float* sWq = (float*)smem;
    float* sBias = sWq + 14*64;
    for (int i = tid; i < 14*64; i += 256) {
        int q = i >> 6, c = i & 63;
        sWq[i] = (q < 10) ? wcls[(size_t)(bn + c)*10 + q]
                          : wwh[(size_t)(bn + c)*4 + (q - 10)];
    }
    if (tid < 64) sBias[tid] = bias[bn + tid];
    __syncthreads();

    #pragma unroll
    for (int mi = 0; mi < 2; ++mi) {
        float psA[14], psB[14];
        #pragma unroll
        for (int q = 0; q < 14; ++q) { psA[q] = 0.0f; psB[q] = 0.0f; }
        #pragma unroll
        for (int ni = 0; ni < 4; ++ni) {
            int cl = wn*32 + ni*8 + (lane & 3)*2;
            float b0 = sBias[cl], b1 = sBias[cl+1];
            float hA0 = fmaxf(acc[mi][ni][0] + b0, 0.0f);
            float hA1 = fmaxf(acc[mi][ni][1] + b1, 0.0f);
            float hB0 = fmaxf(acc[mi][ni][2] + b0, 0.0f);
            float hB1 = fmaxf(acc[mi][ni][3] + b1, 0.0f);
            #pragma unroll
            for (int q = 0; q < 14; ++q) {
                float2 ww = *(const float2*)&sWq[q*64 + cl];
                psA[q] += hA0*ww.x + hA1*ww.y;
                psB[q] += hB0*ww.x + hB1*ww.y;
            }
        }
        #pragma unroll
        for (int o = 1; o < 4; o <<= 1) {
            #pragma unroll
            for (int q = 0; q < 14; ++q) {
                psA[q] += __shfl_xor_sync(0xffffffffu, psA[q], o);
                psB[q] += __shfl_xor_sync(0xffffffffu, psB[q], o);
            }
        }
        if ((lane & 3) == 0) {
            int rA = bm + wm*32 + mi*16 + (lane >> 2);
            int rB = rA + 8;
            if (rA < NDET) {
                #pragma unroll
                for (int q = 0; q < 14; ++q) {
                    float* dst = (q < 10) ? &out[OFF_S2CLS + (size_t)rA*10 + q]
                                          : &out[OFF_S2WH  + (size_t)rA*4  + (q-10)];
                    atomicAdd(dst, psA[q]);
                }
            }
            if (rB < NDET) {
                #pragma unroll
                for (int q = 0; q < 14; ++q) {
                    float* dst = (q < 10) ? &out[OFF_S2CLS + (size_t)rB*10 + q]
                                          : &out[OFF_S2WH  + (size_t)rB*4  + (q-10)];
                    atomicAdd(dst, psB[q]);
                }
            }
        }
    }
}

// ---------------- launch ----------------
extern "C" void kernel_launch(void* const* d_in, const int* in_sizes, int n_in,
                              void* d_out, int out_size) {
    const float* feat  = (const float*)d_in[0];
    const float* hm    = (const float*)d_in[1];
    const float* wh    = (const float*)d_in[2];
    const float* offs  = (const float*)d_in[3];
    const float* wfc1  = (const float*)d_in[4];
    const float* bfc1  = (const float*)d_in[5];
    const float* wcls  = (const float*)d_in[6];
    const float* bcls  = (const float*)d_in[7];
    const float* wwh   = (const float*)d_in[8];
    const float* bwh   = (const float*)d_in[9];
    float* out = (float*)d_out;

    k_front<<<NB_FRONT, 256>>>(hm, feat, wh, offs, wfc1, bcls, bwh, out);
    k_gemm_mma<<<dim3(MPAD/BM, HID/BN), 256>>>(bfc1, wcls, wwh, out);
}

// round 13
// speedup vs baseline: 1.6945x; 1.0862x over previous
#include <cuda_runtime.h>
#include <cuda_bf16.h>
#include <stdint.h>

#define BS 8
#define CH 256
#define HH 128
#define WW 128
#define HW (HH*WW)          /* 16384 */
#define NA 9
#define KTOP 100
#define NDET (BS*KTOP)      /* 800 */
#define FDIM (CH*NA)        /* 2304 */
#define KSPL (3*FDIM)       /* 6912 */
#define MPAD 896            /* 7*128 */
#define HID 1024
#define NBINS 4096
#define CAND 512
#define SAFE_BIN 4088
#define BHW (NA*HW)         /* 147456 */
#define HMTOT (BS*BHW)      /* 1179648 */
#define HBLK 18

/* front-kernel block layout (bid-ordered: producers before consumers) */
#define NB_HIST (HBLK*BS)              /* 144 */
#define SEL_BASE NB_HIST               /* 144 */
#define ROI_BASE (SEL_BASE + BS)       /* 152 */
#define PREP_BASE (ROI_BASE + NDET)    /* 952 */
#define NB_PREP ((FDIM/64)*(HID/32))   /* 1152 */
#define NB_FRONT (PREP_BASE + NB_PREP) /* 2104 */

#define OFF_HM    0
#define OFF_WH1   1179648
#define OFF_OFF1  1182848
#define OFF_CLS1  1184448
#define OFF_WH2   1185248
#define OFF_OFF2  1188448
#define OFF_S2CLS 1190048
#define OFF_S2WH  1198048
#define OFF_INDS  1201248
#define OFF_VAL   1202048

// ---------------- scratch ----------------
__device__ int                g_hist[BS*NBINS];
__device__ int                g_ccnt[BS];
__device__ unsigned long long g_cand[BS*CAND];
__device__ float              g_boxes[NDET*4];
__device__ int                g_histdone;         // reset in k_stage2
__device__ int                g_boxready[BS];     // reset in k_stage2
__device__ __align__(16) __nv_bfloat16 g_abf[MPAD*KSPL];   // rows >= NDET stay zero forever
__device__ __align__(16) __nv_bfloat16 g_bbf[HID*KSPL];
__device__ float              g_part[2*MPAD*HID]; // split-K partials

__device__ __forceinline__ uint32_t smem_u32(const void* p) {
    uint32_t a;
    asm("{ .reg .u64 t; cvta.to.shared.u64 t, %1; cvt.u32.u64 %0, t; }" : "=r"(a) : "l"(p));
    return a;
}
__device__ __forceinline__ void cp_async16(uint32_t d, const void* s) {
    unsigned long long g;
    asm("cvta.to.global.u64 %0, %1;" : "=l"(g) : "l"(s));
    asm volatile("cp.async.cg.shared.global [%0], [%1], 16;" :: "r"(d), "l"(g));
}
__device__ __forceinline__ void ldmatrix_x4(uint32_t* r, uint32_t addr) {
    asm volatile("ldmatrix.sync.aligned.m8n8.x4.shared.b16 {%0,%1,%2,%3}, [%4];"
        : "=r"(r[0]), "=r"(r[1]), "=r"(r[2]), "=r"(r[3]) : "r"(addr));
}
__device__ __forceinline__ void mma16816(float* d, const uint32_t* a, const uint32_t* b) {
    asm volatile("mma.sync.aligned.m16n8k16.row.col.f32.bf16.bf16.f32 "
        "{%0,%1,%2,%3}, {%4,%5,%6,%7}, {%8,%9}, {%0,%1,%2,%3};"
        : "+f"(d[0]), "+f"(d[1]), "+f"(d[2]), "+f"(d[3])
        : "r"(a[0]), "r"(a[1]), "r"(a[2]), "r"(a[3]), "r"(b[0]), "r"(b[1]));
}
__device__ __forceinline__ int val_bin(float v) {
    int bin = (int)(v * (float)NBINS);
    return bin < 0 ? 0 : (bin > NBINS-1 ? NBINS-1 : bin);
}
__device__ __forceinline__ unsigned long long make_key(float v, int il) {
    int a = il / HW, pix = il - a*HW;
    unsigned iflat = (unsigned)(pix * NA + a);
    return ((unsigned long long)__float_as_uint(v) << 32) | (0xFFFFFFFFu - iflat);
}

// ================ fused front kernel ================
__global__ void __launch_bounds__(256) k_front(const float* __restrict__ hm,
                       const float* __restrict__ feat,
                       const float* __restrict__ wh,  const float* __restrict__ offs,
                       const float* __restrict__ wfc1,
                       float* __restrict__ out) {
    __shared__ union {
        int hist[NBINS];
        struct { unsigned long long sk[CAND]; int thr; int ovf; } sel;
        float prep[64][33];
    } u;
    int bid = blockIdx.x, tid = threadIdx.x;

    // ---------- role 1: hist + copy + candidate collect ----------
    if (bid < NB_HIST) {
        int b = bid / HBLK, xblk = bid % HBLK;
        #pragma unroll
        for (int q = 0; q < NBINS/256; ++q) u.hist[tid + q*256] = 0;
        __syncthreads();
        const int chunk = BHW/4/HBLK;
        int base4 = b*(BHW/4) + xblk*chunk;
        const float4* src = (const float4*)hm + base4;
        float4* dst = (float4*)(out + OFF_HM) + base4;
        int il_base = xblk*chunk*4;
        #pragma unroll
        for (int q = 0; q < chunk/256; ++q) {
            int i = tid + q*256;
            float4 v4 = src[i];
            dst[i] = v4;
            float vv[4] = {v4.x, v4.y, v4.z, v4.w};
            #pragma unroll
            for (int e = 0; e < 4; ++e) {
                int bin = val_bin(vv[e]);
                atomicAdd(&u.hist[bin], 1);
                if (bin >= SAFE_BIN) {
                    unsigned long long key = make_key(vv[e], il_base + i*4 + e);
                    int p = atomicAdd(&g_ccnt[b], 1);
                    if (p < CAND) g_cand[b*CAND + p] = key;
                }
            }
        }
        __syncthreads();
        #pragma unroll
        for (int q = 0; q < NBINS/256; ++q) {
            int i = tid + q*256;
            int c = u.hist[i];
            if (c) atomicAdd(&g_hist[b*NBINS + i], c);
        }
        __threadfence();
        __syncthreads();
        if (tid == 0) atomicAdd(&g_histdone, 1);
        return;
    }

    // ---------- role 2: select ----------
    if (bid < ROI_BASE) {
        int b = bid - SEL_BASE, lane = tid & 31, wid = tid >> 5;
        if (tid == 0) { while (atomicAdd(&g_histdone, 0) < NB_HIST) { } }
        __syncthreads();
        __threadfence();

        int rawcnt = g_ccnt[b];
        int C = rawcnt < CAND ? rawcnt : CAND;
        #pragma unroll
        for (int q = 0; q < CAND/256; ++q) {
            int i = tid + q*256;
            u.sel.sk[i] = (i < C) ? g_cand[b*CAND + i] : 0ULL;
        }
        if (wid == 0) {
            int cum = 0, found = 0, t = 0;
            for (int base = NBINS-32; base >= 0 && !found; base -= 32) {
                int c = g_hist[b*NBINS + base + lane];
                #pragma unroll
                for (int o = 1; o < 32; o <<= 1) {
                    int uu = __shfl_down_sync(0xffffffffu, c, o);
                    if (lane < 32 - o) c += uu;
                }
                unsigned m = __ballot_sync(0xffffffffu, cum + c >= KTOP);
                if (m) { t = base + (31 - __clz(m)); found = 1; }
                else cum += __shfl_sync(0xffffffffu, c, 0);
            }
            if (lane == 0) { u.sel.thr = t; u.sel.ovf = 0; }
        }
        __syncthreads();
        int thr = u.sel.thr;

        if (rawcnt > CAND || thr < SAFE_BIN) {        // exactness fallback
            const float* hb = hm + (size_t)b * BHW;
            for (int i = tid; i < BHW; i += 256) {
                float v = hb[i];
                if (val_bin(v) >= thr) {
                    int p = atomicAdd(&u.sel.ovf, 1);
                    if (p < CAND) u.sel.sk[p] = make_key(v, i);
                }
            }
            __syncthreads();
            int C2 = u.sel.ovf < CAND ? u.sel.ovf : CAND;
            #pragma unroll
            for (int q = 0; q < CAND/256; ++q) {
                int i = tid + q*256;
                if (i >= C2) u.sel.sk[i] = 0ULL;
            }
        }
        for (int i = tid; i < NBINS; i += 256) g_hist[b*NBINS + i] = 0;
        if (tid == 0) g_ccnt[b] = 0;

        for (int k = 2; k <= CAND; k <<= 1)
            for (int j = k >> 1; j > 0; j >>= 1) {
                __syncthreads();
                int idx = ((tid & ~(j - 1)) << 1) | (tid & (j - 1));
                int ixj = idx | j;
                unsigned long long x = u.sel.sk[idx], y = u.sel.sk[ixj];
                bool desc = ((idx & k) == 0);
                if (desc ? (x < y) : (x > y)) { u.sel.sk[idx] = y; u.sel.sk[ixj] = x; }
            }
        __syncthreads();

        if (tid < KTOP) {
            int j = b*KTOP + tid;
            unsigned long long m = u.sel.sk[tid];
            float v = __uint_as_float((unsigned)(m >> 32));
            int iflat = (int)(0xFFFFFFFFu - (unsigned)(m & 0xFFFFFFFFu));
            int cls1 = iflat % NA;
            int pos  = iflat / NA;
            int inds = pos + b * HW;
            int a2 = inds % NA;        // select_tensor batch-0 quirk
            int p2 = inds / NA;
            float w0 = wh[(a2*4+0)*HW + p2];
            float w1 = wh[(a2*4+1)*HW + p2];
            float w2 = wh[(a2*4+2)*HW + p2];
            float w3 = wh[(a2*4+3)*HW + p2];
            float o0 = offs[(a2*2+0)*HW + p2];
            float o1 = offs[(a2*2+1)*HW + p2];
            float xs = (float)(inds % WW) + o0;
            float ys = (float)(inds / WW) + o1;
            g_boxes[j*4+0] = xs + w0; g_boxes[j*4+1] = ys + w1;
            g_boxes[j*4+2] = xs + w2; g_boxes[j*4+3] = ys + w3;
            out[OFF_WH1 + j*4+0] = w0; out[OFF_WH1 + j*4+1] = w1;
            out[OFF_WH1 + j*4+2] = w2; out[OFF_WH1 + j*4+3] = w3;
            out[OFF_WH2 + j*4+0] = w0; out[OFF_WH2 + j*4+1] = w1;
            out[OFF_WH2 + j*4+2] = w2; out[OFF_WH2 + j*4+3] = w3;
            out[OFF_OFF1 + j*2+0] = o0; out[OFF_OFF1 + j*2+1] = o1;
            out[OFF_OFF2 + j*2+0] = o0; out[OFF_OFF2 + j*2+1] = o1;
            out[OFF_CLS1 + j] = (float)cls1;
            out[OFF_INDS + j] = (float)inds;
            out[OFF_VAL  + j] = v;
        }
        __threadfence();
        __syncthreads();
        if (tid == 0) atomicExch(&g_boxready[b], 1);
        return;
    }

    // ---------- role 3: ROI align -> bf16 split A' ----------
    if (bid < PREP_BASE) {
        int j = bid - ROI_BASE;
        int c = tid;
        int b = j / KTOP;
        if (tid == 0) { while (atomicAdd(&g_boxready[b], 0) == 0) { } }
        __syncthreads();
        __threadfence();
        float x1b = g_boxes[j*4+0], y1b = g_boxes[j*4+1];
        float x2b = g_boxes[j*4+2], y2b = g_boxes[j*4+3];
        float rw = fmaxf(x2b - x1b, 1.0f);
        float rh = fmaxf(y2b - y1b, 1.0f);
        float bw = rw / 3.0f;
        float bh = rh / 3.0f;
        const float* fb = feat + ((size_t)b*CH + c) * HW;
        #pragma unroll
        for (int pt = 0; pt < 9; ++pt) {
            int gy = pt / 3, gx = pt % 3;
            float sy = __fadd_rn(y1b, __fmul_rn((float)gy + 0.5f, bh));
            float sx = __fadd_rn(x1b, __fmul_rn((float)gx + 0.5f, bw));
            bool inv = (sy < -1.0f) || (sy > (float)HH) || (sx < -1.0f) || (sx > (float)WW);
            float r = 0.0f;
            if (!inv) {
                float y = fminf(fmaxf(sy, 0.0f), (float)(HH-1));
                float x = fminf(fmaxf(sx, 0.0f), (float)(WW-1));
                int y0 = (int)floorf(y), x0 = (int)floorf(x);
                int y1i = min(y0 + 1, HH-1), x1i = min(x0 + 1, WW-1);
                float ly = __fadd_rn(y, -(float)y0);
                float lx = __fadd_rn(x, -(float)x0);
                float hy = __fadd_rn(1.0f, -ly);
                float hx = __fadd_rn(1.0f, -lx);
                float v00, v01, v10, v11;
                if ((x0 & 1) == 0 && x0 < HH-1) {
                    float2 t0 = *(const float2*)(fb + y0 *WW + x0);
                    float2 t1 = *(const float2*)(fb + y1i*WW + x0);
                    v00 = t0.x; v01 = t0.y; v10 = t1.x; v11 = t1.y;
                } else {
                    v00 = fb[y0 *WW + x0 ]; v01 = fb[y0 *WW + x1i];
                    v10 = fb[y1i*WW + x0 ]; v11 = fb[y1i*WW + x1i];
                }
                r = __fadd_rn(__fadd_rn(__fadd_rn(
                        __fmul_rn(__fmul_rn(hy,hx), v00),
                        __fmul_rn(__fmul_rn(hy,lx), v01)),
                        __fmul_rn(__fmul_rn(ly,hx), v10)),
                        __fmul_rn(__fmul_rn(ly,lx), v11));
            }
            __nv_bfloat16 hi = __float2bfloat16(r);
            __nv_bfloat16 lo = __float2bfloat16(__fadd_rn(r, -__bfloat162float(hi)));
            size_t base = (size_t)j*KSPL + 3*(pt*CH + c);
            g_abf[base+0] = hi;
            g_abf[base+1] = hi;
            g_abf[base+2] = lo;
        }
        return;
    }

    // ---------- role 4: B' prep ----------
    {
        int pid = bid - PREP_BASE;
        int t0 = (pid % (FDIM/64)) * 64, n0 = (pid / (FDIM/64)) * 32;
        int wp = tid >> 5, ln = tid & 31;
        #pragma unroll
        for (int q = 0; q < 8; ++q) {
            int tl = wp*8 + q;
            int t = t0 + tl;
            int pt = t >> 8, c = t & 255;
            u.prep[tl][ln] = wfc1[(size_t)(c*NA + pt)*HID + n0 + ln];
        }
        __syncthreads();
        int n = tid >> 3, tg = tid & 7;
        __nv_bfloat16 obuf[24];
        #pragma unroll
        for (int q = 0; q < 8; ++q) {
            float v = u.prep[tg*8 + q][n];
            __nv_bfloat16 hi = __float2bfloat16(v);
            __nv_bfloat16 lo = __float2bfloat16(v - __bfloat162float(hi));
            obuf[q*3+0] = hi; obuf[q*3+1] = lo; obuf[q*3+2] = hi;
        }
        uint4* dst = (uint4*)((char*)g_bbf + (size_t)(n0 + n)*(KSPL*2) + 6*(size_t)(t0 + tg*8));
        const uint4* sv = (const uint4*)obuf;
        dst[0] = sv[0]; dst[1] = sv[1]; dst[2] = sv[2];
    }
}

// ---------------- fc1 GEMM: 128x64, 2-stage, split-K x2, strength-reduced ----------------
#define BM 128
#define BN 64
#define STAGE_BYTES 24576     /* A 16KB + B 8KB */
#define KT_TOTAL (KSPL/64)    /* 108 */
#define KT_PER (KT_TOTAL/2)   /* 54 */
__global__ void __launch_bounds__(256) k_gemm_mma() {
    __shared__ __align__(1024) char smem[2*STAGE_BYTES];
    int tid = threadIdx.x, lane = tid & 31, w = tid >> 5;
    int bm = blockIdx.x * BM, bn = blockIdx.y * BN;
    int z = blockIdx.z;
    int wm = w >> 1, wn = w & 1;

    // ---- precompute copy addresses (strength reduction) ----
    const char* aPtr[4]; uint32_t aSm[4][2];
    const char* bPtr[2]; uint32_t bSm[2][2];
    {
        const char* aG = (const char*)g_abf + (size_t)bm * (KSPL*2) + (size_t)z*KT_PER*128;
        const char* bG = (const char*)g_bbf + (size_t)bn * (KSPL*2) + (size_t)z*KT_PER*128;
        #pragma unroll
        for (int q = 0; q < 4; ++q) {
            int id = tid + q*256;
            int r = id >> 3, c = id & 7;
            aPtr[q] = aG + (size_t)r*(KSPL*2) + c*16;
            int off = r*128 + ((c ^ (r & 7)) * 16);
            aSm[q][0] = smem_u32(smem + off);
            aSm[q][1] = aSm[q][0] + STAGE_BYTES;
        }
        #pragma unroll
        for (int q = 0; q < 2; ++q) {
            int id = tid + q*256;
            int r = id >> 3, c = id & 7;
            bPtr[q] = bG + (size_t)r*(KSPL*2) + c*16;
            int off = 16384 + r*128 + ((c ^ (r & 7)) * 16);
            bSm[q][0] = smem_u32(smem + off);
            bSm[q][1] = bSm[q][0] + STAGE_BYTES;
        }
    }
    // ---- precompute LDSM row-base addresses ----
    uint32_t aRowA[2][2], bRowA[2][2];   // [stage][frag]
    int x7 = lane & 7;
    int ca_hi = lane >> 4;               // 0/1
    int cb_lo = (lane >> 3) & 1;
    {
        int ra = lane & 15;
        int grp = lane >> 3;
        int rb_in = (grp >> 1)*8 + (lane & 7);
        #pragma unroll
        for (int mi = 0; mi < 2; ++mi) {
            int r = wm*32 + mi*16 + ra;
            aRowA[0][mi] = smem_u32(smem + r*128);
            aRowA[1][mi] = aRowA[0][mi] + STAGE_BYTES;
        }
        #pragma unroll
        for (int nj = 0; nj < 2; ++nj) {
            int r = wn*32 + nj*16 + rb_in;
            bRowA[0][nj] = smem_u32(smem + 16384 + r*128);
            bRowA[1][nj] = bRowA[0][nj] + STAGE_BYTES;
        }
    }

    float acc[2][4][4];
    #pragma unroll
    for (int mi = 0; mi < 2; ++mi)
        #pragma unroll
        for (int ni = 0; ni < 4; ++ni)
            #pragma unroll
            for (int e = 0; e < 4; ++e) acc[mi][ni][e] = 0.0f;

    #define ISSUE_STAGE(st) do {                                               \
        _Pragma("unroll")                                                      \
        for (int q = 0; q < 4; ++q) { cp_async16(aSm[q][st], aPtr[q]); aPtr[q] += 128; } \
        _Pragma("unroll")                                                      \
        for (int q = 0; q < 2; ++q) { cp_async16(bSm[q][st], bPtr[q]); bPtr[q] += 128; } \
        asm volatile("cp.async.commit_group;" ::: "memory");                   \
    } while (0)

    ISSUE_STAGE(0);

    for (int kt = 0; kt < KT_PER; ++kt) {
        int st = kt & 1;
        if (kt + 1 < KT_PER) {
            ISSUE_STAGE(st ^ 1);
            asm volatile("cp.async.wait_group 1;" ::: "memory");
        } else {
            asm volatile("cp.async.wait_group 0;" ::: "memory");
        }
        __syncthreads();

        uint32_t af[2][2][4], bf[2][2][4];
        // preload kk = 0
        {
            uint32_t cav = (uint32_t)((ca_hi ^ x7) * 16);
            uint32_t cbv = (uint32_t)((cb_lo ^ x7) * 16);
            #pragma unroll
            for (int mi = 0; mi < 2; ++mi) ldmatrix_x4(af[0][mi], aRowA[st][mi] + cav);
            #pragma unroll
            for (int nj = 0; nj < 2; ++nj) ldmatrix_x4(bf[0][nj], bRowA[st][nj] + cbv);
        }
        #pragma unroll
        for (int kk = 0; kk < 4; ++kk) {
            int cur = kk & 1, nxt = cur ^ 1;
            if (kk < 3) {
                uint32_t cav = (uint32_t)((((kk+1)*2 + ca_hi) ^ x7) * 16);
                uint32_t cbv = (uint32_t)((((kk+1)*2 + cb_lo) ^ x7) * 16);
                #pragma unroll
                for (int mi = 0; mi < 2; ++mi) ldmatrix_x4(af[nxt][mi], aRowA[st][mi] + cav);
                #pragma unroll
                for (int nj = 0; nj < 2; ++nj) ldmatrix_x4(bf[nxt][nj], bRowA[st][nj] + cbv);
            }
            #pragma unroll
            for (int mi = 0; mi < 2; ++mi)
                #pragma unroll
                for (int ni = 0; ni < 4; ++ni)
                    mma16816(acc[mi][ni], af[cur][mi], &bf[cur][ni >> 1][(ni & 1) * 2]);
        }
        __syncthreads();
    }

    // ---- store partial accumulators ----
    float* pp = g_part + (size_t)z*MPAD*HID;
    #pragma unroll
    for (int mi = 0; mi < 2; ++mi) {
        int rA = bm + wm*32 + mi*16 + (lane >> 2);
        #pragma unroll
        for (int ni = 0; ni < 4; ++ni) {
            int ccol = bn + wn*32 + ni*8 + (lane & 3)*2;
            *(float2*)&pp[(size_t)rA*HID + ccol]     = make_float2(acc[mi][ni][0], acc[mi][ni][1]);
            *(float2*)&pp[(size_t)(rA+8)*HID + ccol] = make_float2(acc[mi][ni][2], acc[mi][ni][3]);
        }
    }
}

// ---------------- stage2: sum partials + bias + relu + heads ----------------
__global__ void k_stage2(const float* __restrict__ bias,
                         const float* __restrict__ wcls, const float* __restrict__ bcls,
                         const float* __restrict__ wwh,  const float* __restrict__ bwh,
                         float* __restrict__ out) {
    __shared__ float sh[HID];
    __shared__ float red[14][128];
    int j = blockIdx.x;
    int tid = threadIdx.x;   // 128
    if (j == 0 && tid == 0) {          // reset front-kernel flags for next replay
        g_histdone = 0;
        #pragma unroll
        for (int b = 0; b < BS; ++b) g_boxready[b] = 0;
    }
    for (int i = tid; i < HID; i += 128) {
        float v = g_part[(size_t)j*HID + i] + g_part[(size_t)MPAD*HID + (size_t)j*HID + i] + bias[i];
        sh[i] = fmaxf(v, 0.0f);
    }
    __syncthreads();
    float acc[14];
    #pragma unroll
    for (int q = 0; q < 14; ++q) acc[q] = 0.0f;
    for (int i = tid; i < HID; i += 128) {
        float h = sh[i];
        #pragma unroll
        for (int q = 0; q < 10; ++q) acc[q]      += h * wcls[i*10 + q];
        #pragma unroll
        for (int q = 0; q < 4;  ++q) acc[10 + q] += h * wwh [i*4  + q];
    }
    #pragma unroll
    for (int q = 0; q < 14; ++q) red[q][tid] = acc[q];
    __syncthreads();
    if (tid < 14) {
        float s = 0.0f;
        #pragma unroll 8
        for (int t = 0; t < 128; ++t) s += red[tid][t];
        if (tid < 10) out[OFF_S2CLS + j*10 + tid]      = s + bcls[tid];
        else          out[OFF_S2WH  + j*4  + (tid-10)] = s + bwh[tid-10];
    }
}

// ---------------- launch ----------------
extern "C" void kernel_launch(void* const* d_in, const int* in_sizes, int n_in,
                              void* d_out, int out_size) {
    const float* feat  = (const float*)d_in[0];
    const float* hm    = (const float*)d_in[1];
    const float* wh    = (const float*)d_in[2];
    const float* offs  = (const float*)d_in[3];
    const float* wfc1  = (const float*)d_in[4];
    const float* bfc1  = (const float*)d_in[5];
    const float* wcls  = (const float*)d_in[6];
    const float* bcls  = (const float*)d_in[7];
    const float* wwh   = (const float*)d_in[8];
    const float* bwh   = (const float*)d_in[9];
    float* out = (float*)d_out;

    k_front<<<NB_FRONT, 256>>>(hm, feat, wh, offs, wfc1, out);
    k_gemm_mma<<<dim3(MPAD/BM, HID/BN, 2), 256>>>();
    k_stage2<<<NDET, 128>>>(bfc1, wcls, bcls, wwh, bwh, out);
}

// round 14
// speedup vs baseline: 2.3241x; 1.3716x over previous
#include <cuda_runtime.h>
#include <cuda_fp16.h>
#include <stdint.h>

#define BS 8
#define CH 256
#define HH 128
#define WW 128
#define HW (HH*WW)          /* 16384 */
#define NA 9
#define KTOP 100
#define NDET (BS*KTOP)      /* 800 */
#define FDIM (CH*NA)        /* 2304 */
#define KSPL (2*FDIM)       /* 4608 : fp16 [hi,lo] x [hi,hi] */
#define MPAD 896            /* 7*128 */
#define HID 1024
#define NBINS 4096
#define CAND 512
#define SAFE_BIN 4088
#define BHW (NA*HW)         /* 147456 */
#define HMTOT (BS*BHW)      /* 1179648 */
#define HBLK 18
#define NSPLIT 4

/* front-kernel block layout (bid-ordered: producers before consumers) */
#define NB_HIST (HBLK*BS)              /* 144 */
#define SEL_BASE NB_HIST               /* 144 */
#define ROI_BASE (SEL_BASE + BS)       /* 152 */
#define PREP_BASE (ROI_BASE + NDET)    /* 952 */
#define NB_PREP ((FDIM/64)*(HID/32))   /* 1152 */
#define NB_FRONT (PREP_BASE + NB_PREP) /* 2104 */

#define OFF_HM    0
#define OFF_WH1   1179648
#define OFF_OFF1  1182848
#define OFF_CLS1  1184448
#define OFF_WH2   1185248
#define OFF_OFF2  1188448
#define OFF_S2CLS 1190048
#define OFF_S2WH  1198048
#define OFF_INDS  1201248
#define OFF_VAL   1202048

// ---------------- scratch ----------------
__device__ int                g_hist[BS*NBINS];
__device__ int                g_ccnt[BS];
__device__ unsigned long long g_cand[BS*CAND];
__device__ float              g_boxes[NDET*4];
__device__ int                g_histdone;         // reset in k_stage2
__device__ int                g_boxready[BS];     // reset in k_stage2
__device__ __align__(16) __half g_abf[MPAD*KSPL]; // rows >= NDET stay zero forever
__device__ __align__(16) __half g_bbf[HID*KSPL];
__device__ float              g_part[NSPLIT*MPAD*HID];

__device__ __forceinline__ uint32_t smem_u32(const void* p) {
    uint32_t a;
    asm("{ .reg .u64 t; cvta.to.shared.u64 t, %1; cvt.u32.u64 %0, t; }" : "=r"(a) : "l"(p));
    return a;
}
__device__ __forceinline__ void cp_async16(uint32_t d, const void* s) {
    unsigned long long g;
    asm("cvta.to.global.u64 %0, %1;" : "=l"(g) : "l"(s));
    asm volatile("cp.async.cg.shared.global [%0], [%1], 16;" :: "r"(d), "l"(g));
}
__device__ __forceinline__ void ldmatrix_x4(uint32_t* r, uint32_t addr) {
    asm volatile("ldmatrix.sync.aligned.m8n8.x4.shared.b16 {%0,%1,%2,%3}, [%4];"
        : "=r"(r[0]), "=r"(r[1]), "=r"(r[2]), "=r"(r[3]) : "r"(addr));
}
__device__ __forceinline__ void mma16816(float* d, const uint32_t* a, const uint32_t* b) {
    asm volatile("mma.sync.aligned.m16n8k16.row.col.f32.f16.f16.f32 "
        "{%0,%1,%2,%3}, {%4,%5,%6,%7}, {%8,%9}, {%0,%1,%2,%3};"
        : "+f"(d[0]), "+f"(d[1]), "+f"(d[2]), "+f"(d[3])
        : "r"(a[0]), "r"(a[1]), "r"(a[2]), "r"(a[3]), "r"(b[0]), "r"(b[1]));
}
__device__ __forceinline__ int val_bin(float v) {
    int bin = (int)(v * (float)NBINS);
    return bin < 0 ? 0 : (bin > NBINS-1 ? NBINS-1 : bin);
}
__device__ __forceinline__ unsigned long long make_key(float v, int il) {
    int a = il / HW, pix = il - a*HW;
    unsigned iflat = (unsigned)(pix * NA + a);
    return ((unsigned long long)__float_as_uint(v) << 32) | (0xFFFFFFFFu - iflat);
}
__device__ __forceinline__ uint32_t pack_h2(__half lo16, __half hi16) {
    __half2 h2 = __halves2half2(lo16, hi16);
    return *(uint32_t*)&h2;
}

// ================ fused front kernel ================
__global__ void __launch_bounds__(256) k_front(const float* __restrict__ hm,
                       const float* __restrict__ feat,
                       const float* __restrict__ wh,  const float* __restrict__ offs,
                       const float* __restrict__ wfc1,
                       float* __restrict__ out) {
    __shared__ union {
        int hist[NBINS];
        struct { unsigned long long sk[CAND]; int thr; int ovf; } sel;
        float prep[64][33];
    } u;
    int bid = blockIdx.x, tid = threadIdx.x;

    // ---------- role 1: hist + copy + candidate collect ----------
    if (bid < NB_HIST) {
        int b = bid / HBLK, xblk = bid % HBLK;
        #pragma unroll
        for (int q = 0; q < NBINS/256; ++q) u.hist[tid + q*256] = 0;
        __syncthreads();
        const int chunk = BHW/4/HBLK;
        int base4 = b*(BHW/4) + xblk*chunk;
        const float4* src = (const float4*)hm + base4;
        float4* dst = (float4*)(out + OFF_HM) + base4;
        int il_base = xblk*chunk*4;
        #pragma unroll
        for (int q = 0; q < chunk/256; ++q) {
            int i = tid + q*256;
            float4 v4 = src[i];
            dst[i] = v4;
            float vv[4] = {v4.x, v4.y, v4.z, v4.w};
            #pragma unroll
            for (int e = 0; e < 4; ++e) {
                int bin = val_bin(vv[e]);
                atomicAdd(&u.hist[bin], 1);
                if (bin >= SAFE_BIN) {
                    unsigned long long key = make_key(vv[e], il_base + i*4 + e);
                    int p = atomicAdd(&g_ccnt[b], 1);
                    if (p < CAND) g_cand[b*CAND + p] = key;
                }
            }
        }
        __syncthreads();
        #pragma unroll
        for (int q = 0; q < NBINS/256; ++q) {
            int i = tid + q*256;
            int c = u.hist[i];
            if (c) atomicAdd(&g_hist[b*NBINS + i], c);
        }
        __threadfence();
        __syncthreads();
        if (tid == 0) atomicAdd(&g_histdone, 1);
        return;
    }

    // ---------- role 2: select ----------
    if (bid < ROI_BASE) {
        int b = bid - SEL_BASE, lane = tid & 31, wid = tid >> 5;
        if (tid == 0) { while (atomicAdd(&g_histdone, 0) < NB_HIST) { } }
        __syncthreads();
        __threadfence();

        int rawcnt = g_ccnt[b];
        int C = rawcnt < CAND ? rawcnt : CAND;
        #pragma unroll
        for (int q = 0; q < CAND/256; ++q) {
            int i = tid + q*256;
            u.sel.sk[i] = (i < C) ? g_cand[b*CAND + i] : 0ULL;
        }
        if (wid == 0) {
            int cum = 0, found = 0, t = 0;
            for (int base = NBINS-32; base >= 0 && !found; base -= 32) {
                int c = g_hist[b*NBINS + base + lane];
                #pragma unroll
                for (int o = 1; o < 32; o <<= 1) {
                    int uu = __shfl_down_sync(0xffffffffu, c, o);
                    if (lane < 32 - o) c += uu;
                }
                unsigned m = __ballot_sync(0xffffffffu, cum + c >= KTOP);
                if (m) { t = base + (31 - __clz(m)); found = 1; }
                else cum += __shfl_sync(0xffffffffu, c, 0);
            }
            if (lane == 0) { u.sel.thr = t; u.sel.ovf = 0; }
        }
        __syncthreads();
        int thr = u.sel.thr;

        if (rawcnt > CAND || thr < SAFE_BIN) {        // exactness fallback
            const float* hb = hm + (size_t)b * BHW;
            for (int i = tid; i < BHW; i += 256) {
                float v = hb[i];
                if (val_bin(v) >= thr) {
                    int p = atomicAdd(&u.sel.ovf, 1);
                    if (p < CAND) u.sel.sk[p] = make_key(v, i);
                }
            }
            __syncthreads();
            int C2 = u.sel.ovf < CAND ? u.sel.ovf : CAND;
            #pragma unroll
            for (int q = 0; q < CAND/256; ++q) {
                int i = tid + q*256;
                if (i >= C2) u.sel.sk[i] = 0ULL;
            }
        }
        for (int i = tid; i < NBINS; i += 256) g_hist[b*NBINS + i] = 0;
        if (tid == 0) g_ccnt[b] = 0;

        for (int k = 2; k <= CAND; k <<= 1)
            for (int j = k >> 1; j > 0; j >>= 1) {
                __syncthreads();
                int idx = ((tid & ~(j - 1)) << 1) | (tid & (j - 1));
                int ixj = idx | j;
                unsigned long long x = u.sel.sk[idx], y = u.sel.sk[ixj];
                bool desc = ((idx & k) == 0);
                if (desc ? (x < y) : (x > y)) { u.sel.sk[idx] = y; u.sel.sk[ixj] = x; }
            }
        __syncthreads();

        if (tid < KTOP) {
            int j = b*KTOP + tid;
            unsigned long long m = u.sel.sk[tid];
            float v = __uint_as_float((unsigned)(m >> 32));
            int iflat = (int)(0xFFFFFFFFu - (unsigned)(m & 0xFFFFFFFFu));
            int cls1 = iflat % NA;
            int pos  = iflat / NA;
            int inds = pos + b * HW;
            int a2 = inds % NA;        // select_tensor batch-0 quirk
            int p2 = inds / NA;
            float w0 = wh[(a2*4+0)*HW + p2];
            float w1 = wh[(a2*4+1)*HW + p2];
            float w2 = wh[(a2*4+2)*HW + p2];
            float w3 = wh[(a2*4+3)*HW + p2];
            float o0 = offs[(a2*2+0)*HW + p2];
            float o1 = offs[(a2*2+1)*HW + p2];
            float xs = (float)(inds % WW) + o0;
            float ys = (float)(inds / WW) + o1;
            g_boxes[j*4+0] = xs + w0; g_boxes[j*4+1] = ys + w1;
            g_boxes[j*4+2] = xs + w2; g_boxes[j*4+3] = ys + w3;
            out[OFF_WH1 + j*4+0] = w0; out[OFF_WH1 + j*4+1] = w1;
            out[OFF_WH1 + j*4+2] = w2; out[OFF_WH1 + j*4+3] = w3;
            out[OFF_WH2 + j*4+0] = w0; out[OFF_WH2 + j*4+1] = w1;
            out[OFF_WH2 + j*4+2] = w2; out[OFF_WH2 + j*4+3] = w3;
            out[OFF_OFF1 + j*2+0] = o0; out[OFF_OFF1 + j*2+1] = o1;
            out[OFF_OFF2 + j*2+0] = o0; out[OFF_OFF2 + j*2+1] = o1;
            out[OFF_CLS1 + j] = (float)cls1;
            out[OFF_INDS + j] = (float)inds;
            out[OFF_VAL  + j] = v;
        }
        __threadfence();
        __syncthreads();
        if (tid == 0) atomicExch(&g_boxready[b], 1);
        return;
    }

    // ---------- role 3: ROI align -> fp16 [hi,lo] A' ----------
    if (bid < PREP_BASE) {
        int j = bid - ROI_BASE;
        int c = tid;
        int b = j / KTOP;
        if (tid == 0) { while (atomicAdd(&g_boxready[b], 0) == 0) { } }
        __syncthreads();
        __threadfence();
        float x1b = g_boxes[j*4+0], y1b = g_boxes[j*4+1];
        float x2b = g_boxes[j*4+2], y2b = g_boxes[j*4+3];
        float rw = fmaxf(x2b - x1b, 1.0f);
        float rh = fmaxf(y2b - y1b, 1.0f);
        float bw = rw / 3.0f;
        float bh = rh / 3.0f;
        const float* fb = feat + ((size_t)b*CH + c) * HW;
        uint32_t* arow = (uint32_t*)(g_abf + (size_t)j*KSPL);
        #pragma unroll
        for (int pt = 0; pt < 9; ++pt) {
            int gy = pt / 3, gx = pt % 3;
            float sy = __fadd_rn(y1b, __fmul_rn((float)gy + 0.5f, bh));
            float sx = __fadd_rn(x1b, __fmul_rn((float)gx + 0.5f, bw));
            bool inv = (sy < -1.0f) || (sy > (float)HH) || (sx < -1.0f) || (sx > (float)WW);
            float r = 0.0f;
            if (!inv) {
                float y = fminf(fmaxf(sy, 0.0f), (float)(HH-1));
                float x = fminf(fmaxf(sx, 0.0f), (float)(WW-1));
                int y0 = (int)floorf(y), x0 = (int)floorf(x);
                int y1i = min(y0 + 1, HH-1), x1i = min(x0 + 1, WW-1);
                float ly = __fadd_rn(y, -(float)y0);
                float lx = __fadd_rn(x, -(float)x0);
                float hy = __fadd_rn(1.0f, -ly);
                float hx = __fadd_rn(1.0f, -lx);
                float v00, v01, v10, v11;
                if ((x0 & 1) == 0 && x0 < HH-1) {
                    float2 t0 = *(const float2*)(fb + y0 *WW + x0);
                    float2 t1 = *(const float2*)(fb + y1i*WW + x0);
                    v00 = t0.x; v01 = t0.y; v10 = t1.x; v11 = t1.y;
                } else {
                    v00 = fb[y0 *WW + x0 ]; v01 = fb[y0 *WW + x1i];
                    v10 = fb[y1i*WW + x0 ]; v11 = fb[y1i*WW + x1i];
                }
                r = __fadd_rn(__fadd_rn(__fadd_rn(
                        __fmul_rn(__fmul_rn(hy,hx), v00),
                        __fmul_rn(__fmul_rn(hy,lx), v01)),
                        __fmul_rn(__fmul_rn(ly,hx), v10)),
                        __fmul_rn(__fmul_rn(ly,lx), v11));
            }
            __half hi = __float2half(r);
            __half lo = __float2half(__fadd_rn(r, -__half2float(hi)));
            arow[pt*CH + c] = pack_h2(hi, lo);   // [hi, lo] in K order
        }
        return;
    }

    // ---------- role 4: B' prep: [hi, hi] ----------
    {
        int pid = bid - PREP_BASE;
        int t0 = (pid % (FDIM/64)) * 64, n0 = (pid / (FDIM/64)) * 32;
        int wp = tid >> 5, ln = tid & 31;
        #pragma unroll
        for (int q = 0; q < 8; ++q) {
            int tl = wp*8 + q;
            int t = t0 + tl;
            int pt = t >> 8, c = t & 255;
            u.prep[tl][ln] = wfc1[(size_t)(c*NA + pt)*HID + n0 + ln];
        }
        __syncthreads();
        int n = tid >> 3, tg = tid & 7;
        uint32_t obuf[8];
        #pragma unroll
        for (int q = 0; q < 8; ++q) {
            __half hi = __float2half(u.prep[tg*8 + q][n]);
            obuf[q] = pack_h2(hi, hi);
        }
        uint4* dst = (uint4*)((char*)g_bbf + (size_t)(n0 + n)*(KSPL*2) + 4*(size_t)(t0 + tg*8));
        dst[0] = *(uint4*)&obuf[0];
        dst[1] = *(uint4*)&obuf[4];
    }
}

// ---------------- fc1 GEMM: 128x64, 2-stage, split-K x4, strength-reduced ----------------
#define BM 128
#define BN 64
#define STAGE_BYTES 24576     /* A 16KB + B 8KB */
#define KT_TOTAL (KSPL/64)    /* 72 */
#define KT_PER (KT_TOTAL/NSPLIT)  /* 18 */
__global__ void __launch_bounds__(256) k_gemm_mma() {
    __shared__ __align__(1024) char smem[2*STAGE_BYTES];
    int tid = threadIdx.x, lane = tid & 31, w = tid >> 5;
    int bm = blockIdx.x * BM, bn = blockIdx.y * BN;
    int z = blockIdx.z;
    int wm = w >> 1, wn = w & 1;

    // ---- precompute copy addresses ----
    const char* aPtr[4]; uint32_t aSm[4][2];
    const char* bPtr[2]; uint32_t bSm[2][2];
    {
        const char* aG = (const char*)g_abf + (size_t)bm * (KSPL*2) + (size_t)z*KT_PER*128;
        const char* bG = (const char*)g_bbf + (size_t)bn * (KSPL*2) + (size_t)z*KT_PER*128;
        #pragma unroll
        for (int q = 0; q < 4; ++q) {
            int id = tid + q*256;
            int r = id >> 3, c = id & 7;
            aPtr[q] = aG + (size_t)r*(KSPL*2) + c*16;
            int off = r*128 + ((c ^ (r & 7)) * 16);
            aSm[q][0] = smem_u32(smem + off);
            aSm[q][1] = aSm[q][0] + STAGE_BYTES;
        }
        #pragma unroll
        for (int q = 0; q < 2; ++q) {
            int id = tid + q*256;
            int r = id >> 3, c = id & 7;
            bPtr[q] = bG + (size_t)r*(KSPL*2) + c*16;
            int off = 16384 + r*128 + ((c ^ (r & 7)) * 16);
            bSm[q][0] = smem_u32(smem + off);
            bSm[q][1] = bSm[q][0] + STAGE_BYTES;
        }
    }
    // ---- precompute LDSM row-base addresses ----
    uint32_t aRowA[2][2], bRowA[2][2];   // [stage][frag]
    int x7 = lane & 7;
    int ca_hi = lane >> 4;
    int cb_lo = (lane >> 3) & 1;
    {
        int ra = lane & 15;
        int grp = lane >> 3;
        int rb_in = (grp >> 1)*8 + (lane & 7);
        #pragma unroll
        for (int mi = 0; mi < 2; ++mi) {
            int r = wm*32 + mi*16 + ra;
            aRowA[0][mi] = smem_u32(smem + r*128);
            aRowA[1][mi] = aRowA[0][mi] + STAGE_BYTES;
        }
        #pragma unroll
        for (int nj = 0; nj < 2; ++nj) {
            int r = wn*32 + nj*16 + rb_in;
            bRowA[0][nj] = smem_u32(smem + 16384 + r*128);
            bRowA[1][nj] = bRowA[0][nj] + STAGE_BYTES;
        }
    }

    float acc[2][4][4];
    #pragma unroll
    for (int mi = 0; mi < 2; ++mi)
        #pragma unroll
        for (int ni = 0; ni < 4; ++ni)
            #pragma unroll
            for (int e = 0; e < 4; ++e) acc[mi][ni][e] = 0.0f;

    #define ISSUE_STAGE(st) do {                                               \
        _Pragma("unroll")                                                      \
        for (int q = 0; q < 4; ++q) { cp_async16(aSm[q][st], aPtr[q]); aPtr[q] += 128; } \
        _Pragma("unroll")                                                      \
        for (int q = 0; q < 2; ++q) { cp_async16(bSm[q][st], bPtr[q]); bPtr[q] += 128; } \
        asm volatile("cp.async.commit_group;" ::: "memory");                   \
    } while (0)

    ISSUE_STAGE(0);

    for (int kt = 0; kt < KT_PER; ++kt) {
        int st = kt & 1;
        if (kt + 1 < KT_PER) {
            ISSUE_STAGE(st ^ 1);
            asm volatile("cp.async.wait_group 1;" ::: "memory");
        } else {
            asm volatile("cp.async.wait_group 0;" ::: "memory");
        }
        __syncthreads();

        uint32_t af[2][2][4], bf[2][2][4];
        {
            uint32_t cav = (uint32_t)((ca_hi ^ x7) * 16);
            uint32_t cbv = (uint32_t)((cb_lo ^ x7) * 16);
            #pragma unroll
            for (int mi = 0; mi < 2; ++mi) ldmatrix_x4(af[0][mi], aRowA[st][mi] + cav);
            #pragma unroll
            for (int nj = 0; nj < 2; ++nj) ldmatrix_x4(bf[0][nj], bRowA[st][nj] + cbv);
        }
        #pragma unroll
        for (int kk = 0; kk < 4; ++kk) {
            int cur = kk & 1, nxt = cur ^ 1;
            if (kk < 3) {
                uint32_t cav = (uint32_t)((((kk+1)*2 + ca_hi) ^ x7) * 16);
                uint32_t cbv = (uint32_t)((((kk+1)*2 + cb_lo) ^ x7) * 16);
                #pragma unroll
                for (int mi = 0; mi < 2; ++mi) ldmatrix_x4(af[nxt][mi], aRowA[st][mi] + cav);
                #pragma unroll
                for (int nj = 0; nj < 2; ++nj) ldmatrix_x4(bf[nxt][nj], bRowA[st][nj] + cbv);
            }
            #pragma unroll
            for (int mi = 0; mi < 2; ++mi)
                #pragma unroll
                for (int ni = 0; ni < 4; ++ni)
                    mma16816(acc[mi][ni], af[cur][mi], &bf[cur][ni >> 1][(ni & 1) * 2]);
        }
        __syncthreads();
    }

    // ---- store partial accumulators ----
    float* pp = g_part + (size_t)z*MPAD*HID;
    #pragma unroll
    for (int mi = 0; mi < 2; ++mi) {
        int rA = bm + wm*32 + mi*16 + (lane >> 2);
        #pragma unroll
        for (int ni = 0; ni < 4; ++ni) {
            int ccol = bn + wn*32 + ni*8 + (lane & 3)*2;
            *(float2*)&pp[(size_t)rA*HID + ccol]     = make_float2(acc[mi][ni][0], acc[mi][ni][1]);
            *(float2*)&pp[(size_t)(rA+8)*HID + ccol] = make_float2(acc[mi][ni][2], acc[mi][ni][3]);
        }
    }
}

// ---------------- stage2: sum partials + bias + relu + heads ----------------
__global__ void k_stage2(const float* __restrict__ bias,
                         const float* __restrict__ wcls, const float* __restrict__ bcls,
                         const float* __restrict__ wwh,  const float* __restrict__ bwh,
                         float* __restrict__ out) {
    __shared__ float sh[HID];
    __shared__ float red[14][128];
    int j = blockIdx.x;
    int tid = threadIdx.x;   // 128
    if (j == 0 && tid == 0) {          // reset front-kernel flags for next replay
        g_histdone = 0;
        #pragma unroll
        for (int b = 0; b < BS; ++b) g_boxready[b] = 0;
    }
    for (int i = tid; i < HID; i += 128) {
        float v = bias[i];
        #pragma unroll
        for (int z = 0; z < NSPLIT; ++z)
            v += g_part[(size_t)z*MPAD*HID + (size_t)j*HID + i];
        sh[i] = fmaxf(v, 0.0f);
    }
    __syncthreads();
    float acc[14];
    #pragma unroll
    for (int q = 0; q < 14; ++q) acc[q] = 0.0f;
    for (int i = tid; i < HID; i += 128) {
        float h = sh[i];
        #pragma unroll
        for (int q = 0; q < 10; ++q) acc[q]      += h * wcls[i*10 + q];
        #pragma unroll
        for (int q = 0; q < 4;  ++q) acc[10 + q] += h * wwh [i*4  + q];
    }
    #pragma unroll
    for (int q = 0; q < 14; ++q) red[q][tid] = acc[q];
    __syncthreads();
    if (tid < 14) {
        float s = 0.0f;
        #pragma unroll 8
        for (int t = 0; t < 128; ++t) s += red[tid][t];
        if (tid < 10) out[OFF_S2CLS + j*10 + tid]      = s + bcls[tid];
        else          out[OFF_S2WH  + j*4  + (tid-10)] = s + bwh[tid-10];
    }
}

// ---------------- launch ----------------
extern "C" void kernel_launch(void* const* d_in, const int* in_sizes, int n_in,
                              void* d_out, int out_size) {
    const float* feat  = (const float*)d_in[0];
    const float* hm    = (const float*)d_in[1];
    const float* wh    = (const float*)d_in[2];
    const float* offs  = (const float*)d_in[3];
    const float* wfc1  = (const float*)d_in[4];
    const float* bfc1  = (const float*)d_in[5];
    const float* wcls  = (const float*)d_in[6];
    const float* bcls  = (const float*)d_in[7];
    const float* wwh   = (const float*)d_in[8];
    const float* bwh   = (const float*)d_in[9];
    float* out = (float*)d_out;

    k_front<<<NB_FRONT, 256>>>(hm, feat, wh, offs, wfc1, out);
    k_gemm_mma<<<dim3(MPAD/BM, HID/BN, NSPLIT), 256>>>();
    k_stage2<<<NDET, 128>>>(bfc1, wcls, bcls, wwh, bwh, out);
}

// round 15
// speedup vs baseline: 2.7506x; 1.1835x over previous
#include <cuda_runtime.h>
#include <cuda_fp16.h>
#include <stdint.h>

#define BS 8
#define CH 256
#define HH 128
#define WW 128
#define HW (HH*WW)          /* 16384 */
#define NA 9
#define KTOP 100
#define NDET (BS*KTOP)      /* 800 */
#define FDIM (CH*NA)        /* 2304 */
#define KSPL FDIM           /* 2304 : plain fp16 [hi] x [hi] */
#define MPAD 896            /* 7*128 */
#define HID 1024
#define NBINS 4096
#define CAND 512
#define SAFE_BIN 4088
#define BHW (NA*HW)         /* 147456 */
#define HMTOT (BS*BHW)      /* 1179648 */
#define HBLK 18
#define NSPLIT 2

/* front-kernel block layout (bid-ordered: producers before consumers) */
#define NB_HIST (HBLK*BS)              /* 144 */
#define SEL_BASE NB_HIST               /* 144 */
#define ROI_BASE (SEL_BASE + BS)       /* 152 */
#define PREP_BASE (ROI_BASE + NDET)    /* 952 */
#define NB_PREP ((FDIM/64)*(HID/32))   /* 1152 */
#define NB_FRONT (PREP_BASE + NB_PREP) /* 2104 */

#define OFF_HM    0
#define OFF_WH1   1179648
#define OFF_OFF1  1182848
#define OFF_CLS1  1184448
#define OFF_WH2   1185248
#define OFF_OFF2  1188448
#define OFF_S2CLS 1190048
#define OFF_S2WH  1198048
#define OFF_INDS  1201248
#define OFF_VAL   1202048

// ---------------- scratch ----------------
__device__ int                g_hist[BS*NBINS];
__device__ int                g_ccnt[BS];
__device__ unsigned long long g_cand[BS*CAND];
__device__ float              g_boxes[NDET*4];
__device__ int                g_histdone_b[BS];   // per-batch; reset in k_stage2
__device__ int                g_boxready[BS];     // reset in k_stage2
__device__ __align__(16) __half g_abf[MPAD*KSPL]; // rows >= NDET stay zero forever
__device__ __align__(16) __half g_bbf[HID*KSPL];
__device__ float              g_part[NSPLIT*MPAD*HID];

__device__ __forceinline__ uint32_t smem_u32(const void* p) {
    uint32_t a;
    asm("{ .reg .u64 t; cvta.to.shared.u64 t, %1; cvt.u32.u64 %0, t; }" : "=r"(a) : "l"(p));
    return a;
}
__device__ __forceinline__ void cp_async16(uint32_t d, const void* s) {
    unsigned long long g;
    asm("cvta.to.global.u64 %0, %1;" : "=l"(g) : "l"(s));
    asm volatile("cp.async.cg.shared.global [%0], [%1], 16;" :: "r"(d), "l"(g));
}
__device__ __forceinline__ void ldmatrix_x4(uint32_t* r, uint32_t addr) {
    asm volatile("ldmatrix.sync.aligned.m8n8.x4.shared.b16 {%0,%1,%2,%3}, [%4];"
        : "=r"(r[0]), "=r"(r[1]), "=r"(r[2]), "=r"(r[3]) : "r"(addr));
}
__device__ __forceinline__ void mma16816(float* d, const uint32_t* a, const uint32_t* b) {
    asm volatile("mma.sync.aligned.m16n8k16.row.col.f32.f16.f16.f32 "
        "{%0,%1,%2,%3}, {%4,%5,%6,%7}, {%8,%9}, {%0,%1,%2,%3};"
        : "+f"(d[0]), "+f"(d[1]), "+f"(d[2]), "+f"(d[3])
        : "r"(a[0]), "r"(a[1]), "r"(a[2]), "r"(a[3]), "r"(b[0]), "r"(b[1]));
}
__device__ __forceinline__ int val_bin(float v) {
    int bin = (int)(v * (float)NBINS);
    return bin < 0 ? 0 : (bin > NBINS-1 ? NBINS-1 : bin);
}
__device__ __forceinline__ unsigned long long make_key(float v, int il) {
    int a = il / HW, pix = il - a*HW;
    unsigned iflat = (unsigned)(pix * NA + a);
    return ((unsigned long long)__float_as_uint(v) << 32) | (0xFFFFFFFFu - iflat);
}

// ================ fused front kernel ================
__global__ void __launch_bounds__(256) k_front(const float* __restrict__ hm,
                       const float* __restrict__ feat,
                       const float* __restrict__ wh,  const float* __restrict__ offs,
                       const float* __restrict__ wfc1,
                       float* __restrict__ out) {
    __shared__ union {
        int hist[NBINS];
        struct { unsigned long long sk[CAND]; int thr; int ovf; } sel;
        float prep[64][33];
    } u;
    int bid = blockIdx.x, tid = threadIdx.x;

    // ---------- role 1: hist + copy + candidate collect ----------
    if (bid < NB_HIST) {
        int b = bid / HBLK, xblk = bid % HBLK;
        #pragma unroll
        for (int q = 0; q < NBINS/256; ++q) u.hist[tid + q*256] = 0;
        __syncthreads();
        const int chunk = BHW/4/HBLK;
        int base4 = b*(BHW/4) + xblk*chunk;
        const float4* src = (const float4*)hm + base4;
        float4* dst = (float4*)(out + OFF_HM) + base4;
        int il_base = xblk*chunk*4;
        #pragma unroll
        for (int q = 0; q < chunk/256; ++q) {
            int i = tid + q*256;
            float4 v4 = src[i];
            dst[i] = v4;
            float vv[4] = {v4.x, v4.y, v4.z, v4.w};
            #pragma unroll
            for (int e = 0; e < 4; ++e) {
                int bin = val_bin(vv[e]);
                atomicAdd(&u.hist[bin], 1);
                if (bin >= SAFE_BIN) {
                    unsigned long long key = make_key(vv[e], il_base + i*4 + e);
                    int p = atomicAdd(&g_ccnt[b], 1);
                    if (p < CAND) g_cand[b*CAND + p] = key;
                }
            }
        }
        __syncthreads();
        #pragma unroll
        for (int q = 0; q < NBINS/256; ++q) {
            int i = tid + q*256;
            int c = u.hist[i];
            if (c) atomicAdd(&g_hist[b*NBINS + i], c);
        }
        __threadfence();
        __syncthreads();
        if (tid == 0) atomicAdd(&g_histdone_b[b], 1);
        return;
    }

    // ---------- role 2: select (waits only for its own batch's hist blocks) ----------
    if (bid < ROI_BASE) {
        int b = bid - SEL_BASE, lane = tid & 31, wid = tid >> 5;
        if (tid == 0) { while (atomicAdd(&g_histdone_b[b], 0) < HBLK) { } }
        __syncthreads();
        __threadfence();

        int rawcnt = g_ccnt[b];
        int C = rawcnt < CAND ? rawcnt : CAND;
        #pragma unroll
        for (int q = 0; q < CAND/256; ++q) {
            int i = tid + q*256;
            u.sel.sk[i] = (i < C) ? g_cand[b*CAND + i] : 0ULL;
        }
        if (wid == 0) {
            int cum = 0, found = 0, t = 0;
            for (int base = NBINS-32; base >= 0 && !found; base -= 32) {
                int c = g_hist[b*NBINS + base + lane];
                #pragma unroll
                for (int o = 1; o < 32; o <<= 1) {
                    int uu = __shfl_down_sync(0xffffffffu, c, o);
                    if (lane < 32 - o) c += uu;
                }
                unsigned m = __ballot_sync(0xffffffffu, cum + c >= KTOP);
                if (m) { t = base + (31 - __clz(m)); found = 1; }
                else cum += __shfl_sync(0xffffffffu, c, 0);
            }
            if (lane == 0) { u.sel.thr = t; u.sel.ovf = 0; }
        }
        __syncthreads();
        int thr = u.sel.thr;

        if (rawcnt > CAND || thr < SAFE_BIN) {        // exactness fallback
            const float* hb = hm + (size_t)b * BHW;
            for (int i = tid; i < BHW; i += 256) {
                float v = hb[i];
                if (val_bin(v) >= thr) {
                    int p = atomicAdd(&u.sel.ovf, 1);
                    if (p < CAND) u.sel.sk[p] = make_key(v, i);
                }
            }
            __syncthreads();
            int C2 = u.sel.ovf < CAND ? u.sel.ovf : CAND;
            #pragma unroll
            for (int q = 0; q < CAND/256; ++q) {
                int i = tid + q*256;
                if (i >= C2) u.sel.sk[i] = 0ULL;
            }
        }
        for (int i = tid; i < NBINS; i += 256) g_hist[b*NBINS + i] = 0;
        if (tid == 0) g_ccnt[b] = 0;

        for (int k = 2; k <= CAND; k <<= 1)
            for (int j = k >> 1; j > 0; j >>= 1) {
                __syncthreads();
                int idx = ((tid & ~(j - 1)) << 1) | (tid & (j - 1));
                int ixj = idx | j;
                unsigned long long x = u.sel.sk[idx], y = u.sel.sk[ixj];
                bool desc = ((idx & k) == 0);
                if (desc ? (x < y) : (x > y)) { u.sel.sk[idx] = y; u.sel.sk[ixj] = x; }
            }
        __syncthreads();

        if (tid < KTOP) {
            int j = b*KTOP + tid;
            unsigned long long m = u.sel.sk[tid];
            float v = __uint_as_float((unsigned)(m >> 32));
            int iflat = (int)(0xFFFFFFFFu - (unsigned)(m & 0xFFFFFFFFu));
            int cls1 = iflat % NA;
            int pos  = iflat / NA;
            int inds = pos + b * HW;
            int a2 = inds % NA;        // select_tensor batch-0 quirk
            int p2 = inds / NA;
            float w0 = wh[(a2*4+0)*HW + p2];
            float w1 = wh[(a2*4+1)*HW + p2];
            float w2 = wh[(a2*4+2)*HW + p2];
            float w3 = wh[(a2*4+3)*HW + p2];
            float o0 = offs[(a2*2+0)*HW + p2];
            float o1 = offs[(a2*2+1)*HW + p2];
            float xs = (float)(inds % WW) + o0;
            float ys = (float)(inds / WW) + o1;
            g_boxes[j*4+0] = xs + w0; g_boxes[j*4+1] = ys + w1;
            g_boxes[j*4+2] = xs + w2; g_boxes[j*4+3] = ys + w3;
            out[OFF_WH1 + j*4+0] = w0; out[OFF_WH1 + j*4+1] = w1;
            out[OFF_WH1 + j*4+2] = w2; out[OFF_WH1 + j*4+3] = w3;
            out[OFF_WH2 + j*4+0] = w0; out[OFF_WH2 + j*4+1] = w1;
            out[OFF_WH2 + j*4+2] = w2; out[OFF_WH2 + j*4+3] = w3;
            out[OFF_OFF1 + j*2+0] = o0; out[OFF_OFF1 + j*2+1] = o1;
            out[OFF_OFF2 + j*2+0] = o0; out[OFF_OFF2 + j*2+1] = o1;
            out[OFF_CLS1 + j] = (float)cls1;
            out[OFF_INDS + j] = (float)inds;
            out[OFF_VAL  + j] = v;
        }
        __threadfence();
        __syncthreads();
        if (tid == 0) atomicExch(&g_boxready[b], 1);
        return;
    }

    // ---------- role 3: ROI align -> fp16 A' ----------
    if (bid < PREP_BASE) {
        int j = bid - ROI_BASE;
        int c = tid;
        int b = j / KTOP;
        if (tid == 0) { while (atomicAdd(&g_boxready[b], 0) == 0) { } }
        __syncthreads();
        __threadfence();
        float x1b = g_boxes[j*4+0], y1b = g_boxes[j*4+1];
        float x2b = g_boxes[j*4+2], y2b = g_boxes[j*4+3];
        float rw = fmaxf(x2b - x1b, 1.0f);
        float rh = fmaxf(y2b - y1b, 1.0f);
        float bw = rw / 3.0f;
        float bh = rh / 3.0f;
        const float* fb = feat + ((size_t)b*CH + c) * HW;
        __half* arow = g_abf + (size_t)j*KSPL;
        #pragma unroll
        for (int pt = 0; pt < 9; ++pt) {
            int gy = pt / 3, gx = pt % 3;
            float sy = __fadd_rn(y1b, __fmul_rn((float)gy + 0.5f, bh));
            float sx = __fadd_rn(x1b, __fmul_rn((float)gx + 0.5f, bw));
            bool inv = (sy < -1.0f) || (sy > (float)HH) || (sx < -1.0f) || (sx > (float)WW);
            float r = 0.0f;
            if (!inv) {
                float y = fminf(fmaxf(sy, 0.0f), (float)(HH-1));
                float x = fminf(fmaxf(sx, 0.0f), (float)(WW-1));
                int y0 = (int)floorf(y), x0 = (int)floorf(x);
                int y1i = min(y0 + 1, HH-1), x1i = min(x0 + 1, WW-1);
                float ly = __fadd_rn(y, -(float)y0);
                float lx = __fadd_rn(x, -(float)x0);
                float hy = __fadd_rn(1.0f, -ly);
                float hx = __fadd_rn(1.0f, -lx);
                float v00, v01, v10, v11;
                if ((x0 & 1) == 0 && x0 < HH-1) {
                    float2 t0 = *(const float2*)(fb + y0 *WW + x0);
                    float2 t1 = *(const float2*)(fb + y1i*WW + x0);
                    v00 = t0.x; v01 = t0.y; v10 = t1.x; v11 = t1.y;
                } else {
                    v00 = fb[y0 *WW + x0 ]; v01 = fb[y0 *WW + x1i];
                    v10 = fb[y1i*WW + x0 ]; v11 = fb[y1i*WW + x1i];
                }
                r = __fadd_rn(__fadd_rn(__fadd_rn(
                        __fmul_rn(__fmul_rn(hy,hx), v00),
                        __fmul_rn(__fmul_rn(hy,lx), v01)),
                        __fmul_rn(__fmul_rn(ly,hx), v10)),
                        __fmul_rn(__fmul_rn(ly,lx), v11));
            }
            arow[pt*CH + c] = __float2half(r);
        }
        return;
    }

    // ---------- role 4: B' prep (fp16) ----------
    {
        int pid = bid - PREP_BASE;
        int t0 = (pid % (FDIM/64)) * 64, n0 = (pid / (FDIM/64)) * 32;
        int wp = tid >> 5, ln = tid & 31;
        #pragma unroll
        for (int q = 0; q < 8; ++q) {
            int tl = wp*8 + q;
            int t = t0 + tl;
            int pt = t >> 8, c = t & 255;
            u.prep[tl][ln] = wfc1[(size_t)(c*NA + pt)*HID + n0 + ln];
        }
        __syncthreads();
        int n = tid >> 3, tg = tid & 7;
        __half obuf[8];
        #pragma unroll
        for (int q = 0; q < 8; ++q)
            obuf[q] = __float2half(u.prep[tg*8 + q][n]);
        uint4* dst = (uint4*)((char*)g_bbf + (size_t)(n0 + n)*(KSPL*2) + 2*(size_t)(t0 + tg*8));
        dst[0] = *(uint4*)obuf;
    }
}

// ---------------- fc1 GEMM: 128x64, 2-stage, split-K x2, strength-reduced ----------------
#define BM 128
#define BN 64
#define STAGE_BYTES 24576     /* A 16KB + B 8KB */
#define KT_TOTAL (KSPL/64)    /* 36 */
#define KT_PER (KT_TOTAL/NSPLIT)  /* 18 */
__global__ void __launch_bounds__(256) k_gemm_mma() {
    __shared__ __align__(1024) char smem[2*STAGE_BYTES];
    int tid = threadIdx.x, lane = tid & 31, w = tid >> 5;
    int bm = blockIdx.x * BM, bn = blockIdx.y * BN;
    int z = blockIdx.z;
    int wm = w >> 1, wn = w & 1;

    // ---- precompute copy addresses ----
    const char* aPtr[4]; uint32_t aSm[4][2];
    const char* bPtr[2]; uint32_t bSm[2][2];
    {
        const char* aG = (const char*)g_abf + (size_t)bm * (KSPL*2) + (size_t)z*KT_PER*128;
        const char* bG = (const char*)g_bbf + (size_t)bn * (KSPL*2) + (size_t)z*KT_PER*128;
        #pragma unroll
        for (int q = 0; q < 4; ++q) {
            int id = tid + q*256;
            int r = id >> 3, c = id & 7;
            aPtr[q] = aG + (size_t)r*(KSPL*2) + c*16;
            int off = r*128 + ((c ^ (r & 7)) * 16);
            aSm[q][0] = smem_u32(smem + off);
            aSm[q][1] = aSm[q][0] + STAGE_BYTES;
        }
        #pragma unroll
        for (int q = 0; q < 2; ++q) {
            int id = tid + q*256;
            int r = id >> 3, c = id & 7;
            bPtr[q] = bG + (size_t)r*(KSPL*2) + c*16;
            int off = 16384 + r*128 + ((c ^ (r & 7)) * 16);
            bSm[q][0] = smem_u32(smem + off);
            bSm[q][1] = bSm[q][0] + STAGE_BYTES;
        }
    }
    // ---- precompute LDSM row-base addresses ----
    uint32_t aRowA[2][2], bRowA[2][2];   // [stage][frag]
    int x7 = lane & 7;
    int ca_hi = lane >> 4;
    int cb_lo = (lane >> 3) & 1;
    {
        int ra = lane & 15;
        int grp = lane >> 3;
        int rb_in = (grp >> 1)*8 + (lane & 7);
        #pragma unroll
        for (int mi = 0; mi < 2; ++mi) {
            int r = wm*32 + mi*16 + ra;
            aRowA[0][mi] = smem_u32(smem + r*128);
            aRowA[1][mi] = aRowA[0][mi] + STAGE_BYTES;
        }
        #pragma unroll
        for (int nj = 0; nj < 2; ++nj) {
            int r = wn*32 + nj*16 + rb_in;
            bRowA[0][nj] = smem_u32(smem + 16384 + r*128);
            bRowA[1][nj] = bRowA[0][nj] + STAGE_BYTES;
        }
    }

    float acc[2][4][4];
    #pragma unroll
    for (int mi = 0; mi < 2; ++mi)
        #pragma unroll
        for (int ni = 0; ni < 4; ++ni)
            #pragma unroll
            for (int e = 0; e < 4; ++e) acc[mi][ni][e] = 0.0f;

    #define ISSUE_STAGE(st) do {                                               \
        _Pragma("unroll")                                                      \
        for (int q = 0; q < 4; ++q) { cp_async16(aSm[q][st], aPtr[q]); aPtr[q] += 128; } \
        _Pragma("unroll")                                                      \
        for (int q = 0; q < 2; ++q) { cp_async16(bSm[q][st], bPtr[q]); bPtr[q] += 128; } \
        asm volatile("cp.async.commit_group;" ::: "memory");                   \
    } while (0)

    ISSUE_STAGE(0);

    for (int kt = 0; kt < KT_PER; ++kt) {
        int st = kt & 1;
        if (kt + 1 < KT_PER) {
            ISSUE_STAGE(st ^ 1);
            asm volatile("cp.async.wait_group 1;" ::: "memory");
        } else {
            asm volatile("cp.async.wait_group 0;" ::: "memory");
        }
        __syncthreads();

        uint32_t af[2][2][4], bf[2][2][4];
        {
            uint32_t cav = (uint32_t)((ca_hi ^ x7) * 16);
            uint32_t cbv = (uint32_t)((cb_lo ^ x7) * 16);
            #pragma unroll
            for (int mi = 0; mi < 2; ++mi) ldmatrix_x4(af[0][mi], aRowA[st][mi] + cav);
            #pragma unroll
            for (int nj = 0; nj < 2; ++nj) ldmatrix_x4(bf[0][nj], bRowA[st][nj] + cbv);
        }
        #pragma unroll
        for (int kk = 0; kk < 4; ++kk) {
            int cur = kk & 1, nxt = cur ^ 1;
            if (kk < 3) {
                uint32_t cav = (uint32_t)((((kk+1)*2 + ca_hi) ^ x7) * 16);
                uint32_t cbv = (uint32_t)((((kk+1)*2 + cb_lo) ^ x7) * 16);
                #pragma unroll
                for (int mi = 0; mi < 2; ++mi) ldmatrix_x4(af[nxt][mi], aRowA[st][mi] + cav);
                #pragma unroll
                for (int nj = 0; nj < 2; ++nj) ldmatrix_x4(bf[nxt][nj], bRowA[st][nj] + cbv);
            }
            #pragma unroll
            for (int mi = 0; mi < 2; ++mi)
                #pragma unroll
                for (int ni = 0; ni < 4; ++ni)
                    mma16816(acc[mi][ni], af[cur][mi], &bf[cur][ni >> 1][(ni & 1) * 2]);
        }
        __syncthreads();
    }

    // ---- store partial accumulators ----
    float* pp = g_part + (size_t)z*MPAD*HID;
    #pragma unroll
    for (int mi = 0; mi < 2; ++mi) {
        int rA = bm + wm*32 + mi*16 + (lane >> 2);
        #pragma unroll
        for (int ni = 0; ni < 4; ++ni) {
            int ccol = bn + wn*32 + ni*8 + (lane & 3)*2;
            *(float2*)&pp[(size_t)rA*HID + ccol]     = make_float2(acc[mi][ni][0], acc[mi][ni][1]);
            *(float2*)&pp[(size_t)(rA+8)*HID + ccol] = make_float2(acc[mi][ni][2], acc[mi][ni][3]);
        }
    }
}

// ---------------- stage2: sum partials + bias + relu + heads ----------------
__global__ void k_stage2(const float* __restrict__ bias,
                         const float* __restrict__ wcls, const float* __restrict__ bcls,
                         const float* __restrict__ wwh,  const float* __restrict__ bwh,
                         float* __restrict__ out) {
    __shared__ float sh[HID];
    __shared__ float red[14][128];
    int j = blockIdx.x;
    int tid = threadIdx.x;   // 128
    if (j == 0 && tid == 0) {          // reset front-kernel flags for next replay
        #pragma unroll
        for (int b = 0; b < BS; ++b) { g_histdone_b[b] = 0; g_boxready[b] = 0; }
    }
    for (int i = tid; i < HID; i += 128) {
        float v = bias[i];
        #pragma unroll
        for (int z = 0; z < NSPLIT; ++z)
            v += g_part[(size_t)z*MPAD*HID + (size_t)j*HID + i];
        sh[i] = fmaxf(v, 0.0f);
    }
    __syncthreads();
    float acc[14];
    #pragma unroll
    for (int q = 0; q < 14; ++q) acc[q] = 0.0f;
    for (int i = tid; i < HID; i += 128) {
        float h = sh[i];
        #pragma unroll
        for (int q = 0; q < 10; ++q) acc[q]      += h * wcls[i*10 + q];
        #pragma unroll
        for (int q = 0; q < 4;  ++q) acc[10 + q] += h * wwh [i*4  + q];
    }
    #pragma unroll
    for (int q = 0; q < 14; ++q) red[q][tid] = acc[q];
    __syncthreads();
    if (tid < 14) {
        float s = 0.0f;
        #pragma unroll 8
        for (int t = 0; t < 128; ++t) s += red[tid][t];
        if (tid < 10) out[OFF_S2CLS + j*10 + tid]      = s + bcls[tid];
        else          out[OFF_S2WH  + j*4  + (tid-10)] = s + bwh[tid-10];
    }
}

// ---------------- launch ----------------
extern "C" void kernel_launch(void* const* d_in, const int* in_sizes, int n_in,
                              void* d_out, int out_size) {
    const float* feat  = (const float*)d_in[0];
    const float* hm    = (const float*)d_in[1];
    const float* wh    = (const float*)d_in[2];
    const float* offs  = (const float*)d_in[3];
    const float* wfc1  = (const float*)d_in[4];
    const float* bfc1  = (const float*)d_in[5];
    const float* wcls  = (const float*)d_in[6];
    const float* bcls  = (const float*)d_in[7];
    const float* wwh   = (const float*)d_in[8];
    const float* bwh   = (const float*)d_in[9];
    float* out = (float*)d_out;

    k_front<<<NB_FRONT, 256>>>(hm, feat, wh, offs, wfc1, out);
    k_gemm_mma<<<dim3(MPAD/BM, HID/BN, NSPLIT), 256>>>();
    k_stage2<<<NDET, 128>>>(bfc1, wcls, bcls, wwh, bwh, out);
}

// round 16
// speedup vs baseline: 2.7522x; 1.0006x over previous
#include <cuda_runtime.h>
#include <cuda_fp16.h>
#include <stdint.h>

#define BS 8
#define CH 256
#define HH 128
#define WW 128
#define HW (HH*WW)          /* 16384 */
#define NA 9
#define KTOP 100
#define NDET (BS*KTOP)      /* 800 */
#define FDIM (CH*NA)        /* 2304 */
#define KSPL FDIM           /* 2304 : plain fp16 */
#define MPAD 896            /* 7*128 */
#define HID 1024
#define NBINS 4096
#define CAND 512
#define THRESH_F 0.998046875f   /* 4088/4096 */
#define BHW (NA*HW)         /* 147456 */
#define HMTOT (BS*BHW)      /* 1179648 */
#define HBLK 18
#define NSPLIT 2

/* front-kernel block layout (bid-ordered: producers before consumers) */
#define NB_COPY (HBLK*BS)              /* 144 */
#define SEL_BASE NB_COPY               /* 144 */
#define ROI_BASE (SEL_BASE + BS)       /* 152 */
#define PREP_BASE (ROI_BASE + NDET)    /* 952 */
#define NB_PREP ((FDIM/64)*(HID/32))   /* 1152 */
#define NB_FRONT (PREP_BASE + NB_PREP) /* 2104 */

#define OFF_HM    0
#define OFF_WH1   1179648
#define OFF_OFF1  1182848
#define OFF_CLS1  1184448
#define OFF_WH2   1185248
#define OFF_OFF2  1188448
#define OFF_S2CLS 1190048
#define OFF_S2WH  1198048
#define OFF_INDS  1201248
#define OFF_VAL   1202048

// ---------------- scratch ----------------
__device__ int                g_ccnt[BS];
__device__ unsigned long long g_cand[BS*CAND];
__device__ float              g_boxes[NDET*4];
__device__ int                g_copydone_b[BS];   // per-batch; reset in k_stage2
__device__ int                g_boxready[BS];     // reset in k_stage2
__device__ __align__(16) __half g_abf[MPAD*KSPL]; // rows >= NDET stay zero forever
__device__ __align__(16) __half g_bbf[HID*KSPL];
__device__ float              g_part[NSPLIT*MPAD*HID];

__device__ __forceinline__ uint32_t smem_u32(const void* p) {
    uint32_t a;
    asm("{ .reg .u64 t; cvta.to.shared.u64 t, %1; cvt.u32.u64 %0, t; }" : "=r"(a) : "l"(p));
    return a;
}
__device__ __forceinline__ void cp_async16(uint32_t d, const void* s) {
    unsigned long long g;
    asm("cvta.to.global.u64 %0, %1;" : "=l"(g) : "l"(s));
    asm volatile("cp.async.cg.shared.global [%0], [%1], 16;" :: "r"(d), "l"(g));
}
__device__ __forceinline__ void ldmatrix_x4(uint32_t* r, uint32_t addr) {
    asm volatile("ldmatrix.sync.aligned.m8n8.x4.shared.b16 {%0,%1,%2,%3}, [%4];"
        : "=r"(r[0]), "=r"(r[1]), "=r"(r[2]), "=r"(r[3]) : "r"(addr));
}
__device__ __forceinline__ void mma16816(float* d, const uint32_t* a, const uint32_t* b) {
    asm volatile("mma.sync.aligned.m16n8k16.row.col.f32.f16.f16.f32 "
        "{%0,%1,%2,%3}, {%4,%5,%6,%7}, {%8,%9}, {%0,%1,%2,%3};"
        : "+f"(d[0]), "+f"(d[1]), "+f"(d[2]), "+f"(d[3])
        : "r"(a[0]), "r"(a[1]), "r"(a[2]), "r"(a[3]), "r"(b[0]), "r"(b[1]));
}
__device__ __forceinline__ int val_bin(float v) {
    int bin = (int)(v * (float)NBINS);
    return bin < 0 ? 0 : (bin > NBINS-1 ? NBINS-1 : bin);
}
__device__ __forceinline__ unsigned long long make_key(float v, int il) {
    int a = il / HW, pix = il - a*HW;
    unsigned iflat = (unsigned)(pix * NA + a);
    return ((unsigned long long)__float_as_uint(v) << 32) | (0xFFFFFFFFu - iflat);
}

// ================ fused front kernel ================
__global__ void __launch_bounds__(256) k_front(const float* __restrict__ hm,
                       const float* __restrict__ feat,
                       const float* __restrict__ wh,  const float* __restrict__ offs,
                       const float* __restrict__ wfc1,
                       float* __restrict__ out) {
    __shared__ union {
        struct { unsigned long long sk[CAND]; } sel;
        int hist[NBINS];          // fallback only
        float prep[64][33];
    } u;
    __shared__ int s_thr, s_cnt;
    int bid = blockIdx.x, tid = threadIdx.x;

    // ---------- role 1: streaming copy + candidate collect (no histogram) ----------
    if (bid < NB_COPY) {
        int b = bid / HBLK, xblk = bid % HBLK;
        const int chunk = BHW/4/HBLK;                 // 2048 float4
        int base4 = b*(BHW/4) + xblk*chunk;
        const float4* src = (const float4*)hm + base4;
        float4* dst = (float4*)(out + OFF_HM) + base4;
        int il_base = xblk*chunk*4;
        #pragma unroll
        for (int q = 0; q < chunk/256; ++q) {
            int i = tid + q*256;
            float4 v4 = src[i];
            dst[i] = v4;
            float vv[4] = {v4.x, v4.y, v4.z, v4.w};
            #pragma unroll
            for (int e = 0; e < 4; ++e) {
                if (vv[e] >= THRESH_F) {
                    unsigned long long key = make_key(vv[e], il_base + i*4 + e);
                    int p = atomicAdd(&g_ccnt[b], 1);
                    if (p < CAND) g_cand[b*CAND + p] = key;
                }
            }
        }
        __threadfence();
        __syncthreads();
        if (tid == 0) atomicAdd(&g_copydone_b[b], 1);
        return;
    }

    // ---------- role 2: select (waits only for its own batch's copy blocks) ----------
    if (bid < ROI_BASE) {
        int b = bid - SEL_BASE, lane = tid & 31, wid = tid >> 5;
        if (tid == 0) { while (atomicAdd(&g_copydone_b[b], 0) < HBLK) { } }
        __syncthreads();
        __threadfence();

        int rawcnt = g_ccnt[b];
        if (rawcnt >= KTOP && rawcnt <= CAND) {
            // normal path: candidates ARE a superset of the exact top-100
            #pragma unroll
            for (int q = 0; q < CAND/256; ++q) {
                int i = tid + q*256;
                u.sel.sk[i] = (i < rawcnt) ? g_cand[b*CAND + i] : 0ULL;
            }
        } else {
            // exactness fallback (statistically never taken): private histogram
            #pragma unroll
            for (int q = 0; q < NBINS/256; ++q) u.hist[tid + q*256] = 0;
            __syncthreads();
            const float* hb = hm + (size_t)b * BHW;
            for (int i = tid; i < BHW; i += 256)
                atomicAdd(&u.hist[val_bin(hb[i])], 1);
            __syncthreads();
            if (wid == 0) {
                int cum = 0, found = 0, t = 0;
                for (int base = NBINS-32; base >= 0 && !found; base -= 32) {
                    int c = u.hist[base + lane];
                    #pragma unroll
                    for (int o = 1; o < 32; o <<= 1) {
                        int uu = __shfl_down_sync(0xffffffffu, c, o);
                        if (lane < 32 - o) c += uu;
                    }
                    unsigned m = __ballot_sync(0xffffffffu, cum + c >= KTOP);
                    if (m) { t = base + (31 - __clz(m)); found = 1; }
                    else cum += __shfl_sync(0xffffffffu, c, 0);
                }
                if (lane == 0) { s_thr = t; s_cnt = 0; }
            }
            __syncthreads();
            int thr = s_thr;
            __syncthreads();   // hist no longer needed; union reused as sk below
            for (int i = tid; i < BHW; i += 256) {
                float v = hb[i];
                if (val_bin(v) >= thr) {
                    int p = atomicAdd(&s_cnt, 1);
                    if (p < CAND) u.sel.sk[p] = make_key(v, i);
                }
            }
            __syncthreads();
            int C2 = s_cnt < CAND ? s_cnt : CAND;
            #pragma unroll
            for (int q = 0; q < CAND/256; ++q) {
                int i = tid + q*256;
                if (i >= C2) u.sel.sk[i] = 0ULL;
            }
        }
        if (tid == 0) g_ccnt[b] = 0;   // reset for next replay
        __syncthreads();

        // bitonic sort descending (512 elems, 256 threads)
        for (int k = 2; k <= CAND; k <<= 1)
            for (int j = k >> 1; j > 0; j >>= 1) {
                __syncthreads();
                int idx = ((tid & ~(j - 1)) << 1) | (tid & (j - 1));
                int ixj = idx | j;
                unsigned long long x = u.sel.sk[idx], y = u.sel.sk[ixj];
                bool desc = ((idx & k) == 0);
                if (desc ? (x < y) : (x > y)) { u.sel.sk[idx] = y; u.sel.sk[ixj] = x; }
            }
        __syncthreads();

        if (tid < KTOP) {
            int j = b*KTOP + tid;
            unsigned long long m = u.sel.sk[tid];
            float v = __uint_as_float((unsigned)(m >> 32));
            int iflat = (int)(0xFFFFFFFFu - (unsigned)(m & 0xFFFFFFFFu));
            int cls1 = iflat % NA;
            int pos  = iflat / NA;
            int inds = pos + b * HW;
            int a2 = inds % NA;        // select_tensor batch-0 quirk
            int p2 = inds / NA;
            float w0 = wh[(a2*4+0)*HW + p2];
            float w1 = wh[(a2*4+1)*HW + p2];
            float w2 = wh[(a2*4+2)*HW + p2];
            float w3 = wh[(a2*4+3)*HW + p2];
            float o0 = offs[(a2*2+0)*HW + p2];
            float o1 = offs[(a2*2+1)*HW + p2];
            float xs = (float)(inds % WW) + o0;
            float ys = (float)(inds / WW) + o1;
            g_boxes[j*4+0] = xs + w0; g_boxes[j*4+1] = ys + w1;
            g_boxes[j*4+2] = xs + w2; g_boxes[j*4+3] = ys + w3;
            out[OFF_WH1 + j*4+0] = w0; out[OFF_WH1 + j*4+1] = w1;
            out[OFF_WH1 + j*4+2] = w2; out[OFF_WH1 + j*4+3] = w3;
            out[OFF_WH2 + j*4+0] = w0; out[OFF_WH2 + j*4+1] = w1;
            out[OFF_WH2 + j*4+2] = w2; out[OFF_WH2 + j*4+3] = w3;
            out[OFF_OFF1 + j*2+0] = o0; out[OFF_OFF1 + j*2+1] = o1;
            out[OFF_OFF2 + j*2+0] = o0; out[OFF_OFF2 + j*2+1] = o1;
            out[OFF_CLS1 + j] = (float)cls1;
            out[OFF_INDS + j] = (float)inds;
            out[OFF_VAL  + j] = v;
        }
        __threadfence();
        __syncthreads();
        if (tid == 0) atomicExch(&g_boxready[b], 1);
        return;
    }

    // ---------- role 3: ROI align -> fp16 A' ----------
    if (bid < PREP_BASE) {
        int j = bid - ROI_BASE;
        int c = tid;
        int b = j / KTOP;
        if (tid == 0) { while (atomicAdd(&g_boxready[b], 0) == 0) { } }
        __syncthreads();
        __threadfence();
        float x1b = g_boxes[j*4+0], y1b = g_boxes[j*4+1];
        float x2b = g_boxes[j*4+2], y2b = g_boxes[j*4+3];
        float rw = fmaxf(x2b - x1b, 1.0f);
        float rh = fmaxf(y2b - y1b, 1.0f);
        float bw = rw / 3.0f;
        float bh = rh / 3.0f;
        const float* fb = feat + ((size_t)b*CH + c) * HW;
        __half* arow = g_abf + (size_t)j*KSPL;
        #pragma unroll
        for (int pt = 0; pt < 9; ++pt) {
            int gy = pt / 3, gx = pt % 3;
            float sy = __fadd_rn(y1b, __fmul_rn((float)gy + 0.5f, bh));
            float sx = __fadd_rn(x1b, __fmul_rn((float)gx + 0.5f, bw));
            bool inv = (sy < -1.0f) || (sy > (float)HH) || (sx < -1.0f) || (sx > (float)WW);
            float r = 0.0f;
            if (!inv) {
                float y = fminf(fmaxf(sy, 0.0f), (float)(HH-1));
                float x = fminf(fmaxf(sx, 0.0f), (float)(WW-1));
                int y0 = (int)floorf(y), x0 = (int)floorf(x);
                int y1i = min(y0 + 1, HH-1), x1i = min(x0 + 1, WW-1);
                float ly = __fadd_rn(y, -(float)y0);
                float lx = __fadd_rn(x, -(float)x0);
                float hy = __fadd_rn(1.0f, -ly);
                float hx = __fadd_rn(1.0f, -lx);
                float v00, v01, v10, v11;
                if ((x0 & 1) == 0 && x0 < HH-1) {
                    float2 t0 = *(const float2*)(fb + y0 *WW + x0);
                    float2 t1 = *(const float2*)(fb + y1i*WW + x0);
                    v00 = t0.x; v01 = t0.y; v10 = t1.x; v11 = t1.y;
                } else {
                    v00 = fb[y0 *WW + x0 ]; v01 = fb[y0 *WW + x1i];
                    v10 = fb[y1i*WW + x0 ]; v11 = fb[y1i*WW + x1i];
                }
                r = __fadd_rn(__fadd_rn(__fadd_rn(
                        __fmul_rn(__fmul_rn(hy,hx), v00),
                        __fmul_rn(__fmul_rn(hy,lx), v01)),
                        __fmul_rn(__fmul_rn(ly,hx), v10)),
                        __fmul_rn(__fmul_rn(ly,lx), v11));
            }
            arow[pt*CH + c] = __float2half(r);
        }
        return;
    }

    // ---------- role 4: B' prep (fp16) ----------
    {
        int pid = bid - PREP_BASE;
        int t0 = (pid % (FDIM/64)) * 64, n0 = (pid / (FDIM/64)) * 32;
        int wp = tid >> 5, ln = tid & 31;
        #pragma unroll
        for (int q = 0; q < 8; ++q) {
            int tl = wp*8 + q;
            int t = t0 + tl;
            int pt = t >> 8, c = t & 255;
            u.prep[tl][ln] = wfc1[(size_t)(c*NA + pt)*HID + n0 + ln];
        }
        __syncthreads();
        int n = tid >> 3, tg = tid & 7;
        __half obuf[8];
        #pragma unroll
        for (int q = 0; q < 8; ++q)
            obuf[q] = __float2half(u.prep[tg*8 + q][n]);
        uint4* dst = (uint4*)((char*)g_bbf + (size_t)(n0 + n)*(KSPL*2) + 2*(size_t)(t0 + tg*8));
        dst[0] = *(uint4*)obuf;
    }
}

// ---------------- fc1 GEMM: 128x64, 2-stage, split-K x2, strength-reduced ----------------
#define BM 128
#define BN 64
#define STAGE_BYTES 24576     /* A 16KB + B 8KB */
#define KT_TOTAL (KSPL/64)    /* 36 */
#define KT_PER (KT_TOTAL/NSPLIT)  /* 18 */
__global__ void __launch_bounds__(256) k_gemm_mma() {
    __shared__ __align__(1024) char smem[2*STAGE_BYTES];
    int tid = threadIdx.x, lane = tid & 31, w = tid >> 5;
    int bm = blockIdx.x * BM, bn = blockIdx.y * BN;
    int z = blockIdx.z;
    int wm = w >> 1, wn = w & 1;

    const char* aPtr[4]; uint32_t aSm[4][2];
    const char* bPtr[2]; uint32_t bSm[2][2];
    {
        const char* aG = (const char*)g_abf + (size_t)bm * (KSPL*2) + (size_t)z*KT_PER*128;
        const char* bG = (const char*)g_bbf + (size_t)bn * (KSPL*2) + (size_t)z*KT_PER*128;
        #pragma unroll
        for (int q = 0; q < 4; ++q) {
            int id = tid + q*256;
            int r = id >> 3, c = id & 7;
            aPtr[q] = aG + (size_t)r*(KSPL*2) + c*16;
            int off = r*128 + ((c ^ (r & 7)) * 16);
            aSm[q][0] = smem_u32(smem + off);
            aSm[q][1] = aSm[q][0] + STAGE_BYTES;
        }
        #pragma unroll
        for (int q = 0; q < 2; ++q) {
            int id = tid + q*256;
            int r = id >> 3, c = id & 7;
            bPtr[q] = bG + (size_t)r*(KSPL*2) + c*16;
            int off = 16384 + r*128 + ((c ^ (r & 7)) * 16);
            bSm[q][0] = smem_u32(smem + off);
            bSm[q][1] = bSm[q][0] + STAGE_BYTES;
        }
    }
    uint32_t aRowA[2][2], bRowA[2][2];
    int x7 = lane & 7;
    int ca_hi = lane >> 4;
    int cb_lo = (lane >> 3) & 1;
    {
        int ra = lane & 15;
        int grp = lane >> 3;
        int rb_in = (grp >> 1)*8 + (lane & 7);
        #pragma unroll
        for (int mi = 0; mi < 2; ++mi) {
            int r = wm*32 + mi*16 + ra;
            aRowA[0][mi] = smem_u32(smem + r*128);
            aRowA[1][mi] = aRowA[0][mi] + STAGE_BYTES;
        }
        #pragma unroll
        for (int nj = 0; nj < 2; ++nj) {
            int r = wn*32 + nj*16 + rb_in;
            bRowA[0][nj] = smem_u32(smem + 16384 + r*128);
            bRowA[1][nj] = bRowA[0][nj] + STAGE_BYTES;
        }
    }

    float acc[2][4][4];
    #pragma unroll
    for (int mi = 0; mi < 2; ++mi)
        #pragma unroll
        for (int ni = 0; ni < 4; ++ni)
            #pragma unroll
            for (int e = 0; e < 4; ++e) acc[mi][ni][e] = 0.0f;

    #define ISSUE_STAGE(st) do {                                               \
        _Pragma("unroll")                                                      \
        for (int q = 0; q < 4; ++q) { cp_async16(aSm[q][st], aPtr[q]); aPtr[q] += 128; } \
        _Pragma("unroll")                                                      \
        for (int q = 0; q < 2; ++q) { cp_async16(bSm[q][st], bPtr[q]); bPtr[q] += 128; } \
        asm volatile("cp.async.commit_group;" ::: "memory");                   \
    } while (0)

    ISSUE_STAGE(0);

    for (int kt = 0; kt < KT_PER; ++kt) {
        int st = kt & 1;
        if (kt + 1 < KT_PER) {
            ISSUE_STAGE(st ^ 1);
            asm volatile("cp.async.wait_group 1;" ::: "memory");
        } else {
            asm volatile("cp.async.wait_group 0;" ::: "memory");
        }
        __syncthreads();

        uint32_t af[2][2][4], bf[2][2][4];
        {
            uint32_t cav = (uint32_t)((ca_hi ^ x7) * 16);
            uint32_t cbv = (uint32_t)((cb_lo ^ x7) * 16);
            #pragma unroll
            for (int mi = 0; mi < 2; ++mi) ldmatrix_x4(af[0][mi], aRowA[st][mi] + cav);
            #pragma unroll
            for (int nj = 0; nj < 2; ++nj) ldmatrix_x4(bf[0][nj], bRowA[st][nj] + cbv);
        }
        #pragma unroll
        for (int kk = 0; kk < 4; ++kk) {
            int cur = kk & 1, nxt = cur ^ 1;
            if (kk < 3) {
                uint32_t cav = (uint32_t)((((kk+1)*2 + ca_hi) ^ x7) * 16);
                uint32_t cbv = (uint32_t)((((kk+1)*2 + cb_lo) ^ x7) * 16);
                #pragma unroll
                for (int mi = 0; mi < 2; ++mi) ldmatrix_x4(af[nxt][mi], aRowA[st][mi] + cav);
                #pragma unroll
                for (int nj = 0; nj < 2; ++nj) ldmatrix_x4(bf[nxt][nj], bRowA[st][nj] + cbv);
            }
            #pragma unroll
            for (int mi = 0; mi < 2; ++mi)
                #pragma unroll
                for (int ni = 0; ni < 4; ++ni)
                    mma16816(acc[mi][ni], af[cur][mi], &bf[cur][ni >> 1][(ni & 1) * 2]);
        }
        __syncthreads();
    }

    float* pp = g_part + (size_t)z*MPAD*HID;
    #pragma unroll
    for (int mi = 0; mi < 2; ++mi) {
        int rA = bm + wm*32 + mi*16 + (lane >> 2);
        #pragma unroll
        for (int ni = 0; ni < 4; ++ni) {
            int ccol = bn + wn*32 + ni*8 + (lane & 3)*2;
            *(float2*)&pp[(size_t)rA*HID + ccol]     = make_float2(acc[mi][ni][0], acc[mi][ni][1]);
            *(float2*)&pp[(size_t)(rA+8)*HID + ccol] = make_float2(acc[mi][ni][2], acc[mi][ni][3]);
        }
    }
}

// ---------------- stage2: sum partials + bias + relu + heads ----------------
__global__ void k_stage2(const float* __restrict__ bias,
                         const float* __restrict__ wcls, const float* __restrict__ bcls,
                         const float* __restrict__ wwh,  const float* __restrict__ bwh,
                         float* __restrict__ out) {
    __shared__ float sh[HID];
    __shared__ float red[14][128];
    int j = blockIdx.x;
    int tid = threadIdx.x;   // 128
    if (j == 0 && tid == 0) {
        #pragma unroll
        for (int b = 0; b < BS; ++b) { g_copydone_b[b] = 0; g_boxready[b] = 0; }
    }
    for (int i = tid; i < HID; i += 128) {
        float v = bias[i];
        #pragma unroll
        for (int z = 0; z < NSPLIT; ++z)
            v += g_part[(size_t)z*MPAD*HID + (size_t)j*HID + i];
        sh[i] = fmaxf(v, 0.0f);
    }
    __syncthreads();
    float acc[14];
    #pragma unroll
    for (int q = 0; q < 14; ++q) acc[q] = 0.0f;
    for (int i = tid; i < HID; i += 128) {
        float h = sh[i];
        #pragma unroll
        for (int q = 0; q < 10; ++q) acc[q]      += h * wcls[i*10 + q];
        #pragma unroll
        for (int q = 0; q < 4;  ++q) acc[10 + q] += h * wwh [i*4  + q];
    }
    #pragma unroll
    for (int q = 0; q < 14; ++q) red[q][tid] = acc[q];
    __syncthreads();
    if (tid < 14) {
        float s = 0.0f;
        #pragma unroll 8
        for (int t = 0; t < 128; ++t) s += red[tid][t];
        if (tid < 10) out[OFF_S2CLS + j*10 + tid]      = s + bcls[tid];
        else          out[OFF_S2WH  + j*4  + (tid-10)] = s + bwh[tid-10];
    }
}

// ---------------- launch ----------------
extern "C" void kernel_launch(void* const* d_in, const int* in_sizes, int n_in,
                              void* d_out, int out_size) {
    const float* feat  = (const float*)d_in[0];
    const float* hm    = (const float*)d_in[1];
    const float* wh    = (const float*)d_in[2];
    const float* offs  = (const float*)d_in[3];
    const float* wfc1  = (const float*)d_in[4];
    const float* bfc1  = (const float*)d_in[5];
    const float* wcls  = (const float*)d_in[6];
    const float* bcls  = (const float*)d_in[7];
    const float* wwh   = (const float*)d_in[8];
    const float* bwh   = (const float*)d_in[9];
    float* out = (float*)d_out;

    k_front<<<NB_FRONT, 256>>>(hm, feat, wh, offs, wfc1, out);
    k_gemm_mma<<<dim3(MPAD/BM, HID/BN, NSPLIT), 256>>>();
    k_stage2<<<NDET, 128>>>(bfc1, wcls, bcls, wwh, bwh, out);
}

// round 17
// speedup vs baseline: 2.8571x; 1.0381x over previous
#include <cuda_runtime.h>
#include <cuda_fp16.h>
#include <stdint.h>

#define BS 8
#define CH 256
#define HH 128
#define WW 128
#define HW (HH*WW)          /* 16384 */
#define NA 9
#define KTOP 100
#define NDET (BS*KTOP)      /* 800 */
#define FDIM (CH*NA)        /* 2304 */
#define KSPL FDIM           /* 2304 : plain fp16 */
#define MPAD 896            /* 7*128 */
#define HID 1024
#define NBINS 4096
#define CAND 512
#define THRESH_F 0.998046875f   /* 4088/4096 */
#define BHW (NA*HW)         /* 147456 */
#define HMTOT (BS*BHW)      /* 1179648 */
#define HBLK 36
#define NSPLIT 2

/* front-kernel block layout (bid-ordered: producers before consumers) */
#define NB_COPY (HBLK*BS)              /* 288 */
#define SEL_BASE NB_COPY               /* 288 */
#define ROI_BASE (SEL_BASE + BS)       /* 296 */
#define PREP_BASE (ROI_BASE + NDET)    /* 1096 */
#define NB_PREP ((FDIM/64)*(HID/32))   /* 1152 */
#define NB_FRONT (PREP_BASE + NB_PREP) /* 2248 */

/* back-kernel block layout */
#define NB_GEMM (7*16*NSPLIT)          /* 224 */
#define NB_BACK (NB_GEMM + NDET)       /* 1024 */

#define OFF_HM    0
#define OFF_WH1   1179648
#define OFF_OFF1  1182848
#define OFF_CLS1  1184448
#define OFF_WH2   1185248
#define OFF_OFF2  1188448
#define OFF_S2CLS 1190048
#define OFF_S2WH  1198048
#define OFF_INDS  1201248
#define OFF_VAL   1202048

// ---------------- scratch ----------------
__device__ int                g_ccnt[BS];
__device__ unsigned long long g_cand[BS*CAND];
__device__ float              g_boxes[NDET*4];
__device__ int                g_copydone_b[BS];   // reset in back kernel (stage2 j==0)
__device__ int                g_boxready[BS];     // reset in back kernel (stage2 j==0)
__device__ int                g_gdone[7];         // per-bm gemm done counters; reset in k_front
__device__ __align__(16) __half g_abf[MPAD*KSPL]; // rows >= NDET stay zero forever
__device__ __align__(16) __half g_bbf[HID*KSPL];
__device__ float              g_part[NSPLIT*MPAD*HID];

__device__ __forceinline__ uint32_t smem_u32(const void* p) {
    uint32_t a;
    asm("{ .reg .u64 t; cvta.to.shared.u64 t, %1; cvt.u32.u64 %0, t; }" : "=r"(a) : "l"(p));
    return a;
}
__device__ __forceinline__ void cp_async16(uint32_t d, const void* s) {
    unsigned long long g;
    asm("cvta.to.global.u64 %0, %1;" : "=l"(g) : "l"(s));
    asm volatile("cp.async.cg.shared.global [%0], [%1], 16;" :: "r"(d), "l"(g));
}
__device__ __forceinline__ void ldmatrix_x4(uint32_t* r, uint32_t addr) {
    asm volatile("ldmatrix.sync.aligned.m8n8.x4.shared.b16 {%0,%1,%2,%3}, [%4];"
        : "=r"(r[0]), "=r"(r[1]), "=r"(r[2]), "=r"(r[3]) : "r"(addr));
}
__device__ __forceinline__ void mma16816(float* d, const uint32_t* a, const uint32_t* b) {
    asm volatile("mma.sync.aligned.m16n8k16.row.col.f32.f16.f16.f32 "
        "{%0,%1,%2,%3}, {%4,%5,%6,%7}, {%8,%9}, {%0,%1,%2,%3};"
        : "+f"(d[0]), "+f"(d[1]), "+f"(d[2]), "+f"(d[3])
        : "r"(a[0]), "r"(a[1]), "r"(a[2]), "r"(a[3]), "r"(b[0]), "r"(b[1]));
}
__device__ __forceinline__ int val_bin(float v) {
    int bin = (int)(v * (float)NBINS);
    return bin < 0 ? 0 : (bin > NBINS-1 ? NBINS-1 : bin);
}
__device__ __forceinline__ unsigned long long make_key(float v, int il) {
    int a = il / HW, pix = il - a*HW;
    unsigned iflat = (unsigned)(pix * NA + a);
    return ((unsigned long long)__float_as_uint(v) << 32) | (0xFFFFFFFFu - iflat);
}

// ================ fused front kernel ================
__global__ void __launch_bounds__(256) k_front(const float* __restrict__ hm,
                       const float* __restrict__ feat,
                       const float* __restrict__ wh,  const float* __restrict__ offs,
                       const float* __restrict__ wfc1,
                       float* __restrict__ out) {
    __shared__ union {
        struct { unsigned long long sk[CAND]; } sel;
        int hist[NBINS];          // fallback only
        float prep[64][33];
    } u;
    __shared__ int s_thr, s_cnt;
    int bid = blockIdx.x, tid = threadIdx.x;

    // ---------- role 1: streaming copy + candidate collect ----------
    if (bid < NB_COPY) {
        if (bid == 0 && tid == 0) {           // reset back-kernel counters for this replay
            #pragma unroll
            for (int i = 0; i < 7; ++i) g_gdone[i] = 0;
        }
        int b = bid / HBLK, xblk = bid % HBLK;
        const int chunk = BHW/4/HBLK;                 // 1024 float4
        int base4 = b*(BHW/4) + xblk*chunk;
        const float4* src = (const float4*)hm + base4;
        float4* dst = (float4*)(out + OFF_HM) + base4;
        int il_base = xblk*chunk*4;
        #pragma unroll
        for (int q = 0; q < chunk/256; ++q) {
            int i = tid + q*256;
            float4 v4 = src[i];
            dst[i] = v4;
            float vv[4] = {v4.x, v4.y, v4.z, v4.w};
            #pragma unroll
            for (int e = 0; e < 4; ++e) {
                if (vv[e] >= THRESH_F) {
                    unsigned long long key = make_key(vv[e], il_base + i*4 + e);
                    int p = atomicAdd(&g_ccnt[b], 1);
                    if (p < CAND) g_cand[b*CAND + p] = key;
                }
            }
        }
        __threadfence();
        __syncthreads();
        if (tid == 0) atomicAdd(&g_copydone_b[b], 1);
        return;
    }

    // ---------- role 2: select ----------
    if (bid < ROI_BASE) {
        int b = bid - SEL_BASE, lane = tid & 31, wid = tid >> 5;
        if (tid == 0) { while (atomicAdd(&g_copydone_b[b], 0) < HBLK) { } }
        __syncthreads();
        __threadfence();

        int rawcnt = g_ccnt[b];
        if (rawcnt >= KTOP && rawcnt <= CAND) {
            #pragma unroll
            for (int q = 0; q < CAND/256; ++q) {
                int i = tid + q*256;
                u.sel.sk[i] = (i < rawcnt) ? g_cand[b*CAND + i] : 0ULL;
            }
        } else {
            // exactness fallback: private histogram (statistically never taken)
            #pragma unroll
            for (int q = 0; q < NBINS/256; ++q) u.hist[tid + q*256] = 0;
            __syncthreads();
            const float* hb = hm + (size_t)b * BHW;
            for (int i = tid; i < BHW; i += 256)
                atomicAdd(&u.hist[val_bin(hb[i])], 1);
            __syncthreads();
            if (wid == 0) {
                int cum = 0, found = 0, t = 0;
                for (int base = NBINS-32; base >= 0 && !found; base -= 32) {
                    int c = u.hist[base + lane];
                    #pragma unroll
                    for (int o = 1; o < 32; o <<= 1) {
                        int uu = __shfl_down_sync(0xffffffffu, c, o);
                        if (lane < 32 - o) c += uu;
                    }
                    unsigned m = __ballot_sync(0xffffffffu, cum + c >= KTOP);
                    if (m) { t = base + (31 - __clz(m)); found = 1; }
                    else cum += __shfl_sync(0xffffffffu, c, 0);
                }
                if (lane == 0) { s_thr = t; s_cnt = 0; }
            }
            __syncthreads();
            int thr = s_thr;
            __syncthreads();
            const float* hb2 = hm + (size_t)b * BHW;
            for (int i = tid; i < BHW; i += 256) {
                float v = hb2[i];
                if (val_bin(v) >= thr) {
                    int p = atomicAdd(&s_cnt, 1);
                    if (p < CAND) u.sel.sk[p] = make_key(v, i);
                }
            }
            __syncthreads();
            int C2 = s_cnt < CAND ? s_cnt : CAND;
            #pragma unroll
            for (int q = 0; q < CAND/256; ++q) {
                int i = tid + q*256;
                if (i >= C2) u.sel.sk[i] = 0ULL;
            }
        }
        if (tid == 0) g_ccnt[b] = 0;
        __syncthreads();

        for (int k = 2; k <= CAND; k <<= 1)
            for (int j = k >> 1; j > 0; j >>= 1) {
                __syncthreads();
                int idx = ((tid & ~(j - 1)) << 1) | (tid & (j - 1));
                int ixj = idx | j;
                unsigned long long x = u.sel.sk[idx], y = u.sel.sk[ixj];
                bool desc = ((idx & k) == 0);
                if (desc ? (x < y) : (x > y)) { u.sel.sk[idx] = y; u.sel.sk[ixj] = x; }
            }
        __syncthreads();

        if (tid < KTOP) {
            int j = b*KTOP + tid;
            unsigned long long m = u.sel.sk[tid];
            float v = __uint_as_float((unsigned)(m >> 32));
            int iflat = (int)(0xFFFFFFFFu - (unsigned)(m & 0xFFFFFFFFu));
            int cls1 = iflat % NA;
            int pos  = iflat / NA;
            int inds = pos + b * HW;
            int a2 = inds % NA;        // select_tensor batch-0 quirk
            int p2 = inds / NA;
            float w0 = wh[(a2*4+0)*HW + p2];
            float w1 = wh[(a2*4+1)*HW + p2];
            float w2 = wh[(a2*4+2)*HW + p2];
            float w3 = wh[(a2*4+3)*HW + p2];
            float o0 = offs[(a2*2+0)*HW + p2];
            float o1 = offs[(a2*2+1)*HW + p2];
            float xs = (float)(inds % WW) + o0;
            float ys = (float)(inds / WW) + o1;
            g_boxes[j*4+0] = xs + w0; g_boxes[j*4+1] = ys + w1;
            g_boxes[j*4+2] = xs + w2; g_boxes[j*4+3] = ys + w3;
            out[OFF_WH1 + j*4+0] = w0; out[OFF_WH1 + j*4+1] = w1;
            out[OFF_WH1 + j*4+2] = w2; out[OFF_WH1 + j*4+3] = w3;
            out[OFF_WH2 + j*4+0] = w0; out[OFF_WH2 + j*4+1] = w1;
            out[OFF_WH2 + j*4+2] = w2; out[OFF_WH2 + j*4+3] = w3;
            out[OFF_OFF1 + j*2+0] = o0; out[OFF_OFF1 + j*2+1] = o1;
            out[OFF_OFF2 + j*2+0] = o0; out[OFF_OFF2 + j*2+1] = o1;
            out[OFF_CLS1 + j] = (float)cls1;
            out[OFF_INDS + j] = (float)inds;
            out[OFF_VAL  + j] = v;
        }
        __threadfence();
        __syncthreads();
        if (tid == 0) atomicExch(&g_boxready[b], 1);
        return;
    }

    // ---------- role 3: ROI align -> fp16 A' ----------
    if (bid < PREP_BASE) {
        int j = bid - ROI_BASE;
        int c = tid;
        int b = j / KTOP;
        if (tid == 0) { while (atomicAdd(&g_boxready[b], 0) == 0) { } }
        __syncthreads();
        __threadfence();
        float x1b = g_boxes[j*4+0], y1b = g_boxes[j*4+1];
        float x2b = g_boxes[j*4+2], y2b = g_boxes[j*4+3];
        float rw = fmaxf(x2b - x1b, 1.0f);
        float rh = fmaxf(y2b - y1b, 1.0f);
        float bw = rw / 3.0f;
        float bh = rh / 3.0f;
        const float* fb = feat + ((size_t)b*CH + c) * HW;
        __half* arow = g_abf + (size_t)j*KSPL;
        #pragma unroll
        for (int pt = 0; pt < 9; ++pt) {
            int gy = pt / 3, gx = pt % 3;
            float sy = __fadd_rn(y1b, __fmul_rn((float)gy + 0.5f, bh));
            float sx = __fadd_rn(x1b, __fmul_rn((float)gx + 0.5f, bw));
            bool inv = (sy < -1.0f) || (sy > (float)HH) || (sx < -1.0f) || (sx > (float)WW);
            float r = 0.0f;
            if (!inv) {
                float y = fminf(fmaxf(sy, 0.0f), (float)(HH-1));
                float x = fminf(fmaxf(sx, 0.0f), (float)(WW-1));
                int y0 = (int)floorf(y), x0 = (int)floorf(x);
                int y1i = min(y0 + 1, HH-1), x1i = min(x0 + 1, WW-1);
                float ly = __fadd_rn(y, -(float)y0);
                float lx = __fadd_rn(x, -(float)x0);
                float hy = __fadd_rn(1.0f, -ly);
                float hx = __fadd_rn(1.0f, -lx);
                float v00, v01, v10, v11;
                if ((x0 & 1) == 0 && x0 < HH-1) {
                    float2 t0 = *(const float2*)(fb + y0 *WW + x0);
                    float2 t1 = *(const float2*)(fb + y1i*WW + x0);
                    v00 = t0.x; v01 = t0.y; v10 = t1.x; v11 = t1.y;
                } else {
                    v00 = fb[y0 *WW + x0 ]; v01 = fb[y0 *WW + x1i];
                    v10 = fb[y1i*WW + x0 ]; v11 = fb[y1i*WW + x1i];
                }
                r = __fadd_rn(__fadd_rn(__fadd_rn(
                        __fmul_rn(__fmul_rn(hy,hx), v00),
                        __fmul_rn(__fmul_rn(hy,lx), v01)),
                        __fmul_rn(__fmul_rn(ly,hx), v10)),
                        __fmul_rn(__fmul_rn(ly,lx), v11));
            }
            arow[pt*CH + c] = __float2half(r);
        }
        return;
    }

    // ---------- role 4: B' prep (fp16) ----------
    {
        int pid = bid - PREP_BASE;
        int t0 = (pid % (FDIM/64)) * 64, n0 = (pid / (FDIM/64)) * 32;
        int wp = tid >> 5, ln = tid & 31;
        #pragma unroll
        for (int q = 0; q < 8; ++q) {
            int tl = wp*8 + q;
            int t = t0 + tl;
            int pt = t >> 8, c = t & 255;
            u.prep[tl][ln] = wfc1[(size_t)(c*NA + pt)*HID + n0 + ln];
        }
        __syncthreads();
        int n = tid >> 3, tg = tid & 7;
        __half obuf[8];
        #pragma unroll
        for (int q = 0; q < 8; ++q)
            obuf[q] = __float2half(u.prep[tg*8 + q][n]);
        uint4* dst = (uint4*)((char*)g_bbf + (size_t)(n0 + n)*(KSPL*2) + 2*(size_t)(t0 + tg*8));
        dst[0] = *(uint4*)obuf;
    }
}

// ---------------- back kernel: GEMM (split-K x2) + stage2, fused by role ----------------
#define BM 128
#define BN 64
#define STAGE_BYTES 24576
#define KT_TOTAL (KSPL/64)        /* 36 */
#define KT_PER (KT_TOTAL/NSPLIT)  /* 18 */
__global__ void __launch_bounds__(256) k_back(const float* __restrict__ bias,
                       const float* __restrict__ wcls, const float* __restrict__ bcls,
                       const float* __restrict__ wwh,  const float* __restrict__ bwh,
                       float* __restrict__ out) {
    __shared__ __align__(1024) char smem[2*STAGE_BYTES];
    int bid = blockIdx.x, tid = threadIdx.x, lane = tid & 31, w = tid >> 5;

    if (bid < NB_GEMM) {
        // ================= GEMM role =================
        int bmi = bid >> 5;            // 0..6
        int rem = bid & 31;
        int bni = rem >> 1;            // 0..15
        int z   = rem & 1;
        int bm = bmi*BM, bn = bni*BN;
        int wm = w >> 1, wn = w & 1;

        const char* aPtr[4]; uint32_t aSm[4][2];
        const char* bPtr[2]; uint32_t bSm[2][2];
        {
            const char* aG = (const char*)g_abf + (size_t)bm * (KSPL*2) + (size_t)z*KT_PER*128;
            const char* bG = (const char*)g_bbf + (size_t)bn * (KSPL*2) + (size_t)z*KT_PER*128;
            #pragma unroll
            for (int q = 0; q < 4; ++q) {
                int id = tid + q*256;
                int r = id >> 3, c = id & 7;
                aPtr[q] = aG + (size_t)r*(KSPL*2) + c*16;
                int off = r*128 + ((c ^ (r & 7)) * 16);
                aSm[q][0] = smem_u32(smem + off);
                aSm[q][1] = aSm[q][0] + STAGE_BYTES;
            }
            #pragma unroll
            for (int q = 0; q < 2; ++q) {
                int id = tid + q*256;
                int r = id >> 3, c = id & 7;
                bPtr[q] = bG + (size_t)r*(KSPL*2) + c*16;
                int off = 16384 + r*128 + ((c ^ (r & 7)) * 16);
                bSm[q][0] = smem_u32(smem + off);
                bSm[q][1] = bSm[q][0] + STAGE_BYTES;
            }
        }
        uint32_t aRowA[2][2], bRowA[2][2];
        int x7 = lane & 7;
        int ca_hi = lane >> 4;
        int cb_lo = (lane >> 3) & 1;
        {
            int ra = lane & 15;
            int grp = lane >> 3;
            int rb_in = (grp >> 1)*8 + (lane & 7);
            #pragma unroll
            for (int mi = 0; mi < 2; ++mi) {
                int r = wm*32 + mi*16 + ra;
                aRowA[0][mi] = smem_u32(smem + r*128);
                aRowA[1][mi] = aRowA[0][mi] + STAGE_BYTES;
            }
            #pragma unroll
            for (int nj = 0; nj < 2; ++nj) {
                int r = wn*32 + nj*16 + rb_in;
                bRowA[0][nj] = smem_u32(smem + 16384 + r*128);
                bRowA[1][nj] = bRowA[0][nj] + STAGE_BYTES;
            }
        }

        float acc[2][4][4];
        #pragma unroll
        for (int mi = 0; mi < 2; ++mi)
            #pragma unroll
            for (int ni = 0; ni < 4; ++ni)
                #pragma unroll
                for (int e = 0; e < 4; ++e) acc[mi][ni][e] = 0.0f;

        #define ISSUE_STAGE(st) do {                                               \
            _Pragma("unroll")                                                      \
            for (int q = 0; q < 4; ++q) { cp_async16(aSm[q][st], aPtr[q]); aPtr[q] += 128; } \
            _Pragma("unroll")                                                      \
            for (int q = 0; q < 2; ++q) { cp_async16(bSm[q][st], bPtr[q]); bPtr[q] += 128; } \
            asm volatile("cp.async.commit_group;" ::: "memory");                   \
        } while (0)

        ISSUE_STAGE(0);

        for (int kt = 0; kt < KT_PER; ++kt) {
            int st = kt & 1;
            if (kt + 1 < KT_PER) {
                ISSUE_STAGE(st ^ 1);
                asm volatile("cp.async.wait_group 1;" ::: "memory");
            } else {
                asm volatile("cp.async.wait_group 0;" ::: "memory");
            }
            __syncthreads();

            uint32_t af[2][2][4], bf[2][2][4];
            {
                uint32_t cav = (uint32_t)((ca_hi ^ x7) * 16);
                uint32_t cbv = (uint32_t)((cb_lo ^ x7) * 16);
                #pragma unroll
                for (int mi = 0; mi < 2; ++mi) ldmatrix_x4(af[0][mi], aRowA[st][mi] + cav);
                #pragma unroll
                for (int nj = 0; nj < 2; ++nj) ldmatrix_x4(bf[0][nj], bRowA[st][nj] + cbv);
            }
            #pragma unroll
            for (int kk = 0; kk < 4; ++kk) {
                int cur = kk & 1, nxt = cur ^ 1;
                if (kk < 3) {
                    uint32_t cav = (uint32_t)((((kk+1)*2 + ca_hi) ^ x7) * 16);
                    uint32_t cbv = (uint32_t)((((kk+1)*2 + cb_lo) ^ x7) * 16);
                    #pragma unroll
                    for (int mi = 0; mi < 2; ++mi) ldmatrix_x4(af[nxt][mi], aRowA[st][mi] + cav);
                    #pragma unroll
                    for (int nj = 0; nj < 2; ++nj) ldmatrix_x4(bf[nxt][nj], bRowA[st][nj] + cbv);
                }
                #pragma unroll
                for (int mi = 0; mi < 2; ++mi)
                    #pragma unroll
                    for (int ni = 0; ni < 4; ++ni)
                        mma16816(acc[mi][ni], af[cur][mi], &bf[cur][ni >> 1][(ni & 1) * 2]);
            }
            __syncthreads();
        }

        float* pp = g_part + (size_t)z*MPAD*HID;
        #pragma unroll
        for (int mi = 0; mi < 2; ++mi) {
            int rA = bm + wm*32 + mi*16 + (lane >> 2);
            #pragma unroll
            for (int ni = 0; ni < 4; ++ni) {
                int ccol = bn + wn*32 + ni*8 + (lane & 3)*2;
                *(float2*)&pp[(size_t)rA*HID + ccol]     = make_float2(acc[mi][ni][0], acc[mi][ni][1]);
                *(float2*)&pp[(size_t)(rA+8)*HID + ccol] = make_float2(acc[mi][ni][2], acc[mi][ni][3]);
            }
        }
        __threadfence();
        __syncthreads();
        if (tid == 0) atomicAdd(&g_gdone[bmi], 1);
        return;
    }

    // ================= stage2 role =================
    {
        int j = bid - NB_GEMM;          // 0..799
        float* sh  = (float*)smem;                 // HID floats
        float* red = sh + HID;                     // 14*256 floats
        if (j == 0 && tid == 0) {       // reset front flags for next replay
            #pragma unroll
            for (int b = 0; b < BS; ++b) { g_copydone_b[b] = 0; g_boxready[b] = 0; }
        }
        if (tid == 0) { while (atomicAdd(&g_gdone[j >> 7], 0) < 32) { } }
        __syncthreads();
        __threadfence();

        #pragma unroll
        for (int q = 0; q < HID/256; ++q) {
            int i = tid + q*256;
            float v = bias[i];
            #pragma unroll
            for (int z = 0; z < NSPLIT; ++z)
                v += g_part[(size_t)z*MPAD*HID + (size_t)j*HID + i];
            sh[i] = fmaxf(v, 0.0f);
        }
        __syncthreads();
        float acc[14];
        #pragma unroll
        for (int q = 0; q < 14; ++q) acc[q] = 0.0f;
        #pragma unroll
        for (int qq = 0; qq < HID/256; ++qq) {
            int i = tid + qq*256;
            float h = sh[i];
            #pragma unroll
            for (int q = 0; q < 10; ++q) acc[q]      += h * wcls[i*10 + q];
            #pragma unroll
            for (int q = 0; q < 4;  ++q) acc[10 + q] += h * wwh [i*4  + q];
        }
        #pragma unroll
        for (int q = 0; q < 14; ++q) red[q*256 + tid] = acc[q];
        __syncthreads();
        if (tid < 14) {
            float s = 0.0f;
            #pragma unroll 8
            for (int t = 0; t < 256; ++t) s += red[tid*256 + t];
            if (tid < 10) out[OFF_S2CLS + j*10 + tid]      = s + bcls[tid];
            else          out[OFF_S2WH  + j*4  + (tid-10)] = s + bwh[tid-10];
        }
    }
}

// ---------------- launch ----------------
extern "C" void kernel_launch(void* const* d_in, const int* in_sizes, int n_in,
                              void* d_out, int out_size) {
    const float* feat  = (const float*)d_in[0];
    const float* hm    = (const float*)d_in[1];
    const float* wh    = (const float*)d_in[2];
    const float* offs  = (const float*)d_in[3];
    const float* wfc1  = (const float*)d_in[4];
    const float* bfc1  = (const float*)d_in[5];
    const float* wcls  = (const float*)d_in[6];
    const float* bcls  = (const float*)d_in[7];
    const float* wwh   = (const float*)d_in[8];
    const float* bwh   = (const float*)d_in[9];
    float* out = (float*)d_out;

    k_front<<<NB_FRONT, 256>>>(hm, feat, wh, offs, wfc1, out);
    k_back<<<NB_BACK, 256>>>(bfc1, wcls, bcls, wwh, bwh, out);
}